// round 5
// baseline (speedup 1.0000x reference)
#include <cuda_runtime.h>
#include <cuda_fp16.h>
#include <cstdint>
#include <math.h>

#define BB 4
#define LL 2048
#define DD 1024
#define HH 16
#define KK 256
#define DH 64
#define MROWS (BB*LL)   // 8192

// ---- scratch (device globals; no runtime allocation allowed) ----
__device__ float  g_q[BB*LL*DD];          // x @ Wq^T  [B,L,D] f32
__device__ __half g_xh[BB*LL*DD];         // x hi/lo
__device__ __half g_xl[BB*LL*DD];
__device__ __half g_wqh[DD*DD], g_wql[DD*DD];
__device__ __half g_wkh[DD*DD], g_wkl[DD*DD];
__device__ __half g_wvh[DD*DD], g_wvl[DD*DD];
__device__ __half g_woh[DD*DD], g_wol[DD*DD];
__device__ __half g_pkth[KK*LL], g_pktl[KK*LL];   // proj_k^T hi/lo [K,L]
__device__ __half g_pvth[KK*LL], g_pvtl[KK*LL];
__device__ __half g_xkth[BB*DD*LL], g_xktl[BB*DD*LL];  // (xWk^T)^T hi/lo [B,D,L]
__device__ __half g_xvth[BB*DD*LL], g_xvtl[BB*DD*LL];
__device__ float  g_keys2[2*BB*DD*KK];    // split-K partials
__device__ float  g_vals2[2*BB*KK*DD];
__device__ float  g_keys_t[BB*DD*KK];     // [B,D,K] f32
__device__ float  g_vals[BB*KK*DD];       // [B,K,D] f32
__device__ __half g_ctxh[BB*LL*DD], g_ctxl[BB*LL*DD];  // attention out hi/lo

// ============================================================
// helpers
// ============================================================
__device__ __forceinline__ uint32_t smem_u32(const void* p) {
    uint32_t a;
    asm("{ .reg .u64 t; cvta.to.shared.u64 t, %1; cvt.u32.u64 %0, t; }"
        : "=r"(a) : "l"(p));
    return a;
}
__device__ __forceinline__ void ldsm4(uint32_t* r, uint32_t addr) {
    asm volatile("ldmatrix.sync.aligned.m8n8.x4.shared.b16 {%0,%1,%2,%3}, [%4];"
        : "=r"(r[0]), "=r"(r[1]), "=r"(r[2]), "=r"(r[3]) : "r"(addr));
}
__device__ __forceinline__ void ldsm2(uint32_t* r, uint32_t addr) {
    asm volatile("ldmatrix.sync.aligned.m8n8.x2.shared.b16 {%0,%1}, [%2];"
        : "=r"(r[0]), "=r"(r[1]) : "r"(addr));
}
__device__ __forceinline__ void mma16816(float* c, const uint32_t* a, const uint32_t* b) {
    asm volatile(
        "mma.sync.aligned.m16n8k16.row.col.f32.f16.f16.f32 "
        "{%0,%1,%2,%3}, {%4,%5,%6,%7}, {%8,%9}, {%0,%1,%2,%3};"
        : "+f"(c[0]), "+f"(c[1]), "+f"(c[2]), "+f"(c[3])
        : "r"(a[0]), "r"(a[1]), "r"(a[2]), "r"(a[3]), "r"(b[0]), "r"(b[1]));
}
__device__ __forceinline__ void cp16(uint32_t sa, const void* ga) {
    asm volatile("cp.async.cg.shared.global [%0], [%1], 16;" :: "r"(sa), "l"(ga));
}
#define CP_COMMIT() asm volatile("cp.async.commit_group;" ::: "memory")
#define CP_WAIT0()  asm volatile("cp.async.wait_group 0;" ::: "memory")
#define CP_WAIT1()  asm volatile("cp.async.wait_group 1;" ::: "memory")

// ============================================================
// split-fp16 NT-GEMM, pre-split half planes, 3-stage cp.async pipeline.
// C[m,n] = sum_k A[m,k]*B[n,k], A~Ah+Al, B~Bh+Bl, 3 MMAs (drop lo*lo).
// CTA 128x128, BK=32, 8 warps (warp tile 64x32), 1 CTA/SM (no spills).
// ============================================================
#define TPADH 40                       // halves per smem row (32+8 pad)
#define TILEB (128*TPADH*2)            // 10240 bytes per tile
#define STGB  (4*TILEB)                // 40960 bytes per stage
#define NSTG  3
#define GEMM_SMEM (NSTG*STGB)          // 122880

template<bool BIAS, int OUTMODE>       // OUTMODE 0: f32, 1: half-split
__global__ __launch_bounds__(256, 1)
void gemm_hsplit(const __half* __restrict__ Ah, const __half* __restrict__ Al,
                 long Ab, int lda,
                 const __half* __restrict__ Bh, const __half* __restrict__ Bl,
                 long Bb, int ldb,
                 void* C0, void* C1, long Cb, long Cs, int ldc,
                 const float* __restrict__ bias, int Kd, int ksp)
{
    extern __shared__ __align__(16) char smc[];
    const uint32_t sbase = smem_u32(smc);

    const int tid  = threadIdx.x;
    const int lane = tid & 31;
    const int wid  = tid >> 5;
    const int wm   = wid >> 2;          // 0..1
    const int wn   = wid & 3;           // 0..3

    const int zb = blockIdx.z / ksp;
    const int zs = blockIdx.z % ksp;
    Ah += (size_t)zb * Ab + (size_t)zs * Kd;
    Al += (size_t)zb * Ab + (size_t)zs * Kd;
    Bh += (size_t)zb * Bb + (size_t)zs * Kd;
    Bl += (size_t)zb * Bb + (size_t)zs * Kd;
    const int m0 = blockIdx.y * 128;
    const int n0 = blockIdx.x * 128;

    // per-thread cp.async source pointers / smem offsets (8 x 16B per stage)
    const int seg = tid & 3;
    const int rr  = tid >> 2;           // 0..63
    const __half* gp[8];
    gp[0] = Ah + (size_t)(m0 + rr)      * lda + seg * 8;
    gp[1] = Ah + (size_t)(m0 + rr + 64) * lda + seg * 8;
    gp[2] = Al + (size_t)(m0 + rr)      * lda + seg * 8;
    gp[3] = Al + (size_t)(m0 + rr + 64) * lda + seg * 8;
    gp[4] = Bh + (size_t)(n0 + rr)      * ldb + seg * 8;
    gp[5] = Bh + (size_t)(n0 + rr + 64) * ldb + seg * 8;
    gp[6] = Bl + (size_t)(n0 + rr)      * ldb + seg * 8;
    gp[7] = Bl + (size_t)(n0 + rr + 64) * ldb + seg * 8;
    uint32_t so[8];
    #pragma unroll
    for (int p = 0; p < 8; p++)
        so[p] = (uint32_t)((p >> 1) * TILEB + (rr + (p & 1) * 64) * (TPADH*2) + seg * 16);

    float acc[4][4][4];
    #pragma unroll
    for (int i = 0; i < 4; i++)
        #pragma unroll
        for (int j = 0; j < 4; j++)
            #pragma unroll
            for (int v = 0; v < 4; v++) acc[i][j][v] = 0.f;

    auto load_stage = [&](int s, int it) {
        const int k0 = it * 32;
        const uint32_t base = sbase + s * STGB;
        #pragma unroll
        for (int p = 0; p < 8; p++)
            cp16(base + so[p], gp[p] + k0);
        CP_COMMIT();
    };

    auto compute = [&](int s) {
        const uint32_t aHi = sbase + s * STGB;
        const uint32_t aLo = aHi + TILEB;
        const uint32_t bHi = aHi + 2 * TILEB;
        const uint32_t bLo = aHi + 3 * TILEB;
        #pragma unroll
        for (int ks = 0; ks < 2; ks++) {
            uint32_t ah[4][4], al[4][4], bh[4][2], bl[4][2];
            const int acol = ks * 16 + (lane >> 4) * 8;
            #pragma unroll
            for (int mi = 0; mi < 4; mi++) {
                int r = wm * 64 + mi * 16 + (lane & 15);
                uint32_t off = (uint32_t)(r * TPADH + acol) * 2;
                ldsm4(ah[mi], aHi + off);
                ldsm4(al[mi], aLo + off);
            }
            const int bcol = ks * 16 + ((lane >> 3) & 1) * 8;
            #pragma unroll
            for (int ni = 0; ni < 4; ni++) {
                int r = wn * 32 + ni * 8 + (lane & 7);
                uint32_t off = (uint32_t)(r * TPADH + bcol) * 2;
                ldsm2(bh[ni], bHi + off);
                ldsm2(bl[ni], bLo + off);
            }
            #pragma unroll
            for (int mi = 0; mi < 4; mi++)
                #pragma unroll
                for (int ni = 0; ni < 4; ni++) {
                    mma16816(acc[mi][ni], ah[mi], bh[ni]);
                    mma16816(acc[mi][ni], ah[mi], bl[ni]);
                    mma16816(acc[mi][ni], al[mi], bh[ni]);
                }
        }
    };

    const int iters = Kd / 32;
    load_stage(0, 0);
    if (iters > 1) load_stage(1, 1);

    for (int it = 0; it < iters; it++) {
        // stage `it` must be complete:
        if (it + 2 <= iters) CP_WAIT1(); else CP_WAIT0();
        __syncthreads();                  // also: all warps done with slot (it-1)%3
        if (it + 2 < iters) load_stage((it + 2) % NSTG, it + 2);
        compute(it % NSTG);
    }

    // ---- epilogue ----
    const int g = lane >> 2, tig = lane & 3;
    if (OUTMODE == 0) {
        float* Cf = (float*)C0 + (size_t)zb * Cb + (size_t)zs * Cs;
        #pragma unroll
        for (int mi = 0; mi < 4; mi++) {
            const int r0 = m0 + wm * 64 + mi * 16 + g;
            #pragma unroll
            for (int ni = 0; ni < 4; ni++) {
                const int col = n0 + wn * 32 + ni * 8 + tig * 2;
                float2 v0, v1;
                v0.x = acc[mi][ni][0]; v0.y = acc[mi][ni][1];
                v1.x = acc[mi][ni][2]; v1.y = acc[mi][ni][3];
                if (BIAS) {
                    float2 bv = *(const float2*)(bias + col);
                    v0.x += bv.x; v0.y += bv.y;
                    v1.x += bv.x; v1.y += bv.y;
                }
                *(float2*)(Cf + (size_t)r0 * ldc + col) = v0;
                *(float2*)(Cf + (size_t)(r0 + 8) * ldc + col) = v1;
            }
        }
    } else {
        __half* Ch = (__half*)C0 + (size_t)zb * Cb;
        __half* Cl = (__half*)C1 + (size_t)zb * Cb;
        #pragma unroll
        for (int mi = 0; mi < 4; mi++) {
            const int r0 = m0 + wm * 64 + mi * 16 + g;
            #pragma unroll
            for (int ni = 0; ni < 4; ni++) {
                const int col = n0 + wn * 32 + ni * 8 + tig * 2;
                #pragma unroll
                for (int hv = 0; hv < 2; hv++) {
                    const int r = r0 + hv * 8;
                    float vx = acc[mi][ni][hv*2], vy = acc[mi][ni][hv*2+1];
                    __half2 h = __floats2half2_rn(vx, vy);
                    float2 bk = __half22float2(h);
                    __half2 l = __floats2half2_rn(vx - bk.x, vy - bk.y);
                    *(__half2*)(Ch + (size_t)r * ldc + col) = h;
                    *(__half2*)(Cl + (size_t)r * ldc + col) = l;
                }
            }
        }
    }
}

// ============================================================
// elementwise split f32 -> hi/lo half planes
// ============================================================
__global__ __launch_bounds__(256)
void convert_split(const float* __restrict__ s, __half* __restrict__ hi,
                   __half* __restrict__ lo, int n4)
{
    int i = blockIdx.x * blockDim.x + threadIdx.x;
    if (i >= n4) return;
    float4 v = *(const float4*)(s + i * 4);
    __half2 h0 = __floats2half2_rn(v.x, v.y);
    __half2 h1 = __floats2half2_rn(v.z, v.w);
    float2 b0 = __half22float2(h0);
    float2 b1 = __half22float2(h1);
    __half2 l0 = __floats2half2_rn(v.x - b0.x, v.y - b0.y);
    __half2 l1 = __floats2half2_rn(v.z - b1.x, v.w - b1.y);
    *(__half2*)(hi + i * 4)     = h0;
    *(__half2*)(hi + i * 4 + 2) = h1;
    *(__half2*)(lo + i * 4)     = l0;
    *(__half2*)(lo + i * 4 + 2) = l1;
}

// ============================================================
// proj transpose + split: [L,K] f32 -> [K,L] hi/lo halves
// ============================================================
__global__ __launch_bounds__(256)
void transpose_split(const float* __restrict__ pk, const float* __restrict__ pv,
                     __half* __restrict__ kh, __half* __restrict__ kl,
                     __half* __restrict__ vh, __half* __restrict__ vl)
{
    __shared__ float t[32][33];
    const float* src = blockIdx.z ? pv : pk;
    __half* dh = blockIdx.z ? vh : kh;
    __half* dl = blockIdx.z ? vl : kl;
    int k0 = blockIdx.x * 32, l0 = blockIdx.y * 32;
    int tx = threadIdx.x, ty = threadIdx.y;
    #pragma unroll
    for (int i = 0; i < 32; i += 8)
        t[ty + i][tx] = src[(size_t)(l0 + ty + i) * KK + k0 + tx];
    __syncthreads();
    #pragma unroll
    for (int i = 0; i < 32; i += 8) {
        float v = t[tx][ty + i];
        __half h = __float2half_rn(v);
        __half l = __float2half_rn(v - __half2float(h));
        size_t o = (size_t)(k0 + ty + i) * LL + l0 + tx;
        dh[o] = h; dl[o] = l;
    }
}

// ============================================================
// add split-K partials: o = a + b  (float4)
// ============================================================
__global__ __launch_bounds__(256)
void add2(const float* __restrict__ a, const float* __restrict__ b,
          float* __restrict__ o, int n4)
{
    int i = blockIdx.x * blockDim.x + threadIdx.x;
    if (i >= n4) return;
    float4 x = *(const float4*)(a + i * 4);
    float4 y = *(const float4*)(b + i * 4);
    x.x += y.x; x.y += y.y; x.z += y.z; x.w += y.w;
    *(float4*)(o + i * 4) = x;
}

// ============================================================
// Attention (fp32 SIMT, verified) — emits ctx hi/lo halves
// ============================================================
#define QS_STRIDE 68
#define KS_STRIDE 264
#define VS_STRIDE 68
#define PS_STRIDE 264
#define ATTN_SMEM ((64*QS_STRIDE + 64*KS_STRIDE + 256*VS_STRIDE + 64*PS_STRIDE) * 4)

__global__ __launch_bounds__(256)
void attn_kernel()
{
    extern __shared__ float smf[];
    float* Qs = smf;
    float* Ks = Qs + 64*QS_STRIDE;
    float* Vs = Ks + 64*KS_STRIDE;
    float* Ps = Vs + 256*VS_STRIDE;

    const int b  = blockIdx.z;
    const int h  = blockIdx.y;
    const int l0 = blockIdx.x * 64;
    const int tid = threadIdx.x;

    #pragma unroll
    for (int it = 0; it < 4; it++) {
        int idx = tid + it * 256;
        int r  = idx >> 4;
        int dq = (idx & 15) * 4;
        int l  = l0 + r;
        const float* src = g_q + ((size_t)(b * LL) + h * 128 + (l >> 4)) * DD
                               + (l & 15) * DH + dq;
        *(float4*)&Qs[r * QS_STRIDE + dq] = *(const float4*)src;
    }
    #pragma unroll
    for (int it = 0; it < 16; it++) {
        int idx = tid + it * 256;
        int kd = idx >> 6;
        int c4 = (idx & 63) * 4;
        *(float4*)&Ks[kd * KS_STRIDE + c4] =
            *(const float4*)&g_keys_t[((size_t)b * DD + h * DH + kd) * KK + c4];
    }
    #pragma unroll
    for (int it = 0; it < 16; it++) {
        int idx = tid + it * 256;
        int col = idx >> 4;
        int dq  = (idx & 15) * 4;
        *(float4*)&Vs[col * VS_STRIDE + dq] =
            *(const float4*)&g_vals[((size_t)b * KK + col) * DD + h * DH + dq];
    }
    __syncthreads();

    const int tx = tid & 31, wy = tid >> 5;
    float acc[8][8] = {};
    #pragma unroll 4
    for (int kd = 0; kd < 64; kd++) {
        float a[8], bq[8];
        #pragma unroll
        for (int i = 0; i < 8; i++) a[i] = Qs[(wy*8 + i) * QS_STRIDE + kd];
        *(float4*)&bq[0] = *(const float4*)&Ks[kd * KS_STRIDE + tx*8];
        *(float4*)&bq[4] = *(const float4*)&Ks[kd * KS_STRIDE + tx*8 + 4];
        #pragma unroll
        for (int i = 0; i < 8; i++)
            #pragma unroll
            for (int j = 0; j < 8; j++)
                acc[i][j] += a[i] * bq[j];
    }

    const float SCALE = 0.125f;
    #pragma unroll
    for (int i = 0; i < 8; i++) {
        float mx = -1e30f;
        #pragma unroll
        for (int j = 0; j < 8; j++) {
            acc[i][j] *= SCALE;
            mx = fmaxf(mx, acc[i][j]);
        }
        #pragma unroll
        for (int o = 16; o > 0; o >>= 1)
            mx = fmaxf(mx, __shfl_xor_sync(0xffffffffu, mx, o));
        float s = 0.f;
        #pragma unroll
        for (int j = 0; j < 8; j++) {
            acc[i][j] = __expf(acc[i][j] - mx);
            s += acc[i][j];
        }
        #pragma unroll
        for (int o = 16; o > 0; o >>= 1)
            s += __shfl_xor_sync(0xffffffffu, s, o);
        float inv = 1.f / s;
        float4 p0, p1;
        p0.x = acc[i][0]*inv; p0.y = acc[i][1]*inv; p0.z = acc[i][2]*inv; p0.w = acc[i][3]*inv;
        p1.x = acc[i][4]*inv; p1.y = acc[i][5]*inv; p1.z = acc[i][6]*inv; p1.w = acc[i][7]*inv;
        *(float4*)&Ps[(wy*8 + i) * PS_STRIDE + tx*8    ] = p0;
        *(float4*)&Ps[(wy*8 + i) * PS_STRIDE + tx*8 + 4] = p1;
    }
    __syncthreads();

    float o0[8] = {}, o1[8] = {};
    #pragma unroll 4
    for (int j = 0; j < 256; j++) {
        float2 v = *(const float2*)&Vs[j * VS_STRIDE + tx*2];
        #pragma unroll
        for (int i = 0; i < 8; i++) {
            float p = Ps[(wy*8 + i) * PS_STRIDE + j];
            o0[i] += p * v.x;
            o1[i] += p * v.y;
        }
    }
    #pragma unroll
    for (int i = 0; i < 8; i++) {
        int l = l0 + wy*8 + i;
        size_t o = ((size_t)(b * LL) + l) * DD + h * DH + tx*2;
        __half2 hx = __floats2half2_rn(o0[i], o1[i]);
        float2 bk = __half22float2(hx);
        __half2 lx = __floats2half2_rn(o0[i] - bk.x, o1[i] - bk.y);
        *(__half2*)(g_ctxh + o) = hx;
        *(__half2*)(g_ctxl + o) = lx;
    }
}

// ============================================================
extern "C" void kernel_launch(void* const* d_in, const int* in_sizes, int n_in,
                              void* d_out, int out_size)
{
    const float* x      = (const float*)d_in[0];
    const float* Wq     = (const float*)d_in[1];
    const float* Wk     = (const float*)d_in[2];
    const float* Wv     = (const float*)d_in[3];
    const float* proj_k = (const float*)d_in[4];
    const float* proj_v = (const float*)d_in[5];
    const float* Wo     = (const float*)d_in[6];
    const float* bo     = (const float*)d_in[7];
    float* out = (float*)d_out;

    float *q, *keys2, *vals2, *keys_t, *vals;
    __half *xh, *xl, *wqh, *wql, *wkh, *wkl, *wvh, *wvl, *woh, *wol;
    __half *pkth, *pktl, *pvth, *pvtl, *xkth, *xktl, *xvth, *xvtl, *ctxh, *ctxl;
    cudaGetSymbolAddress((void**)&q,      g_q);
    cudaGetSymbolAddress((void**)&xh,     g_xh);
    cudaGetSymbolAddress((void**)&xl,     g_xl);
    cudaGetSymbolAddress((void**)&wqh,    g_wqh);  cudaGetSymbolAddress((void**)&wql, g_wql);
    cudaGetSymbolAddress((void**)&wkh,    g_wkh);  cudaGetSymbolAddress((void**)&wkl, g_wkl);
    cudaGetSymbolAddress((void**)&wvh,    g_wvh);  cudaGetSymbolAddress((void**)&wvl, g_wvl);
    cudaGetSymbolAddress((void**)&woh,    g_woh);  cudaGetSymbolAddress((void**)&wol, g_wol);
    cudaGetSymbolAddress((void**)&pkth,   g_pkth); cudaGetSymbolAddress((void**)&pktl, g_pktl);
    cudaGetSymbolAddress((void**)&pvth,   g_pvth); cudaGetSymbolAddress((void**)&pvtl, g_pvtl);
    cudaGetSymbolAddress((void**)&xkth,   g_xkth); cudaGetSymbolAddress((void**)&xktl, g_xktl);
    cudaGetSymbolAddress((void**)&xvth,   g_xvth); cudaGetSymbolAddress((void**)&xvtl, g_xvtl);
    cudaGetSymbolAddress((void**)&keys2,  g_keys2);
    cudaGetSymbolAddress((void**)&vals2,  g_vals2);
    cudaGetSymbolAddress((void**)&keys_t, g_keys_t);
    cudaGetSymbolAddress((void**)&vals,   g_vals);
    cudaGetSymbolAddress((void**)&ctxh,   g_ctxh);
    cudaGetSymbolAddress((void**)&ctxl,   g_ctxl);

    cudaFuncSetAttribute(gemm_hsplit<false,0>, cudaFuncAttributeMaxDynamicSharedMemorySize, GEMM_SMEM);
    cudaFuncSetAttribute(gemm_hsplit<false,1>, cudaFuncAttributeMaxDynamicSharedMemorySize, GEMM_SMEM);
    cudaFuncSetAttribute(gemm_hsplit<true,0>,  cudaFuncAttributeMaxDynamicSharedMemorySize, GEMM_SMEM);
    cudaFuncSetAttribute(attn_kernel, cudaFuncAttributeMaxDynamicSharedMemorySize, ATTN_SMEM);

    // ---- pre-split inputs ----
    convert_split<<<(BB*LL*DD/4 + 255)/256, 256>>>(x,  xh,  xl,  BB*LL*DD/4);
    convert_split<<<(DD*DD/4 + 255)/256, 256>>>(Wq, wqh, wql, DD*DD/4);
    convert_split<<<(DD*DD/4 + 255)/256, 256>>>(Wk, wkh, wkl, DD*DD/4);
    convert_split<<<(DD*DD/4 + 255)/256, 256>>>(Wv, wvh, wvl, DD*DD/4);
    convert_split<<<(DD*DD/4 + 255)/256, 256>>>(Wo, woh, wol, DD*DD/4);
    transpose_split<<<dim3(KK/32, LL/32, 2), dim3(32, 8)>>>(
        proj_k, proj_v, pkth, pktl, pvth, pvtl);

    // q = x @ Wq^T -> f32 [8192,1024]
    gemm_hsplit<false,0><<<dim3(DD/128, MROWS/128, 1), 256, GEMM_SMEM>>>(
        xh, xl, 0, DD, wqh, wql, 0, DD, q, nullptr, 0, 0, DD, nullptr, DD, 1);

    // xkt[b] = Wk x_b^T -> half-split [B,D,L]
    gemm_hsplit<false,1><<<dim3(LL/128, DD/128, BB), 256, GEMM_SMEM>>>(
        wkh, wkl, 0, DD, xh, xl, (long)LL*DD, DD,
        xkth, xktl, (long)DD*LL, 0, LL, nullptr, DD, 1);

    // xvt[b]
    gemm_hsplit<false,1><<<dim3(LL/128, DD/128, BB), 256, GEMM_SMEM>>>(
        wvh, wvl, 0, DD, xh, xl, (long)LL*DD, DD,
        xvth, xvtl, (long)DD*LL, 0, LL, nullptr, DD, 1);

    // keys partials: [s][b][D,K]
    gemm_hsplit<false,0><<<dim3(KK/128, DD/128, BB*2), 256, GEMM_SMEM>>>(
        xkth, xktl, (long)DD*LL, LL, pkth, pktl, 0, LL,
        keys2, nullptr, (long)DD*KK, (long)BB*DD*KK, KK, nullptr, LL/2, 2);

    // vals partials: [s][b][K,D]
    gemm_hsplit<false,0><<<dim3(DD/128, KK/128, BB*2), 256, GEMM_SMEM>>>(
        pvth, pvtl, 0, LL, xvth, xvtl, (long)DD*LL, LL,
        vals2, nullptr, (long)KK*DD, (long)BB*KK*DD, DD, nullptr, LL/2, 2);

    // reduce split-K partials
    add2<<<(BB*DD*KK/4 + 255)/256, 256>>>(keys2, keys2 + (size_t)BB*DD*KK, keys_t, BB*DD*KK/4);
    add2<<<(BB*KK*DD/4 + 255)/256, 256>>>(vals2, vals2 + (size_t)BB*KK*DD, vals,  BB*KK*DD/4);

    // attention core (emits ctx hi/lo)
    attn_kernel<<<dim3(LL/64, HH, BB), 256, ATTN_SMEM>>>();

    // out = ctx @ Wo^T + bo
    gemm_hsplit<true,0><<<dim3(DD/128, MROWS/128, 1), 256, GEMM_SMEM>>>(
        ctxh, ctxl, 0, DD, woh, wol, 0, DD, out, nullptr, 0, 0, DD, bo, DD, 1);
}

// round 6
// speedup vs baseline: 1.4300x; 1.4300x over previous
#include <cuda_runtime.h>
#include <cuda_fp16.h>
#include <cstdint>
#include <math.h>

#define BB 4
#define LL 2048
#define DD 1024
#define HH 16
#define KK 256
#define DH 64
#define MROWS (BB*LL)   // 8192

// ---- scratch (device globals; no runtime allocation allowed) ----
__device__ float g_q[BB*LL*DD];        // x @ Wq^T            [B,L,D]
__device__ float g_xkt[BB*DD*LL];      // (x @ Wk^T)^T        [B,D,L]
__device__ float g_xvt[BB*DD*LL];      // (x @ Wv^T)^T        [B,D,L]
__device__ float g_projkt[KK*LL];      // proj_k^T            [K,L]
__device__ float g_projvt[KK*LL];      // proj_v^T            [K,L]
__device__ float g_keys2[2*BB*KK*DD];  // split-K partials
__device__ float g_vals2[2*BB*KK*DD];
__device__ float g_keys[BB*KK*DD];     // keys [B,K,D]
__device__ float g_vals[BB*KK*DD];     // vals [B,K,D]
__device__ float g_ctx[BB*LL*DD];      // attention out       [B,L,D]

// ============================================================
// mma.sync helpers (baseline PTX, works on compute_103)
// ============================================================
__device__ __forceinline__ uint32_t smem_u32(const void* p) {
    uint32_t a;
    asm("{ .reg .u64 t; cvta.to.shared.u64 t, %1; cvt.u32.u64 %0, t; }"
        : "=r"(a) : "l"(p));
    return a;
}
__device__ __forceinline__ void ldsm4(uint32_t* r, uint32_t addr) {
    asm volatile("ldmatrix.sync.aligned.m8n8.x4.shared.b16 {%0,%1,%2,%3}, [%4];"
        : "=r"(r[0]), "=r"(r[1]), "=r"(r[2]), "=r"(r[3]) : "r"(addr));
}
__device__ __forceinline__ void ldsm2(uint32_t* r, uint32_t addr) {
    asm volatile("ldmatrix.sync.aligned.m8n8.x2.shared.b16 {%0,%1}, [%2];"
        : "=r"(r[0]), "=r"(r[1]) : "r"(addr));
}
__device__ __forceinline__ void ldsm2t(uint32_t* r, uint32_t addr) {
    asm volatile("ldmatrix.sync.aligned.m8n8.x2.trans.shared.b16 {%0,%1}, [%2];"
        : "=r"(r[0]), "=r"(r[1]) : "r"(addr));
}
__device__ __forceinline__ void mma16816(float* c, const uint32_t* a, const uint32_t* b) {
    asm volatile(
        "mma.sync.aligned.m16n8k16.row.col.f32.f16.f16.f32 "
        "{%0,%1,%2,%3}, {%4,%5,%6,%7}, {%8,%9}, {%0,%1,%2,%3};"
        : "+f"(c[0]), "+f"(c[1]), "+f"(c[2]), "+f"(c[3])
        : "r"(a[0]), "r"(a[1]), "r"(a[2]), "r"(a[3]), "r"(b[0]), "r"(b[1]));
}

// ============================================================
// split-fp16 NT-GEMM (EXACT R3 structure, measured 159us/big GEMM):
// C[m,n] = sum_k A[m,k]*B[n,k]  (+bias[n]); f32 in, split inline.
// CTA 128x128, BK=32, 8 warps (64x32 warp tiles), 2-stage smem,
// register-staged sync prefetch, 1 CTA/SM.
// Added: batch strides + split-K addressing (zb = z/ksp, zs = z%ksp).
// ============================================================
#define TPAD 40
#define TSZ  (128*TPAD)
#define GEMM_SMEM (8*TSZ*2)      // 81920

template<bool BIAS>
__global__ __launch_bounds__(256, 1)
void gemm_fp16x2(const float* __restrict__ A, long Ab, int lda,
                 const float* __restrict__ B, long Bb, int ldb,
                 float* __restrict__ C, long Cb, long Cs, int ldc,
                 const float* __restrict__ bias, int Kd, int ksp)
{
    extern __shared__ __align__(16) char smc[];
    __half* sm = (__half*)smc;

    const int tid  = threadIdx.x;
    const int lane = tid & 31;
    const int wid  = tid >> 5;
    const int wm   = wid >> 2;
    const int wn   = wid & 3;
    const int g    = lane >> 2;
    const int tig  = lane & 3;

    const int zb = blockIdx.z / ksp;
    const int zs = blockIdx.z % ksp;
    A += (size_t)zb * Ab + (size_t)zs * Kd;
    B += (size_t)zb * Bb + (size_t)zs * Kd;
    C += (size_t)zb * Cb + (size_t)zs * Cs;
    const int m0 = blockIdx.y * 128;
    const int n0 = blockIdx.x * 128;

    const float* Aip = A + (size_t)m0 * lda;
    const float* Bip = B + (size_t)n0 * ldb;

    float acc[4][4][4];
    #pragma unroll
    for (int i = 0; i < 4; i++)
        #pragma unroll
        for (int j = 0; j < 4; j++)
            #pragma unroll
            for (int v = 0; v < 4; v++) acc[i][j][v] = 0.f;

    float4 ra[4], rb[4];

    auto load_regs = [&](int it) {
        const int k0 = it * 32;
        #pragma unroll
        for (int p = 0; p < 4; p++) {
            int idx = tid + p * 256;
            int row = idx >> 3;
            int cc  = (idx & 7) * 4;
            ra[p] = *(const float4*)(Aip + (size_t)row * lda + k0 + cc);
            rb[p] = *(const float4*)(Bip + (size_t)row * ldb + k0 + cc);
        }
    };

    auto store_tiles = [&](int s) {
        __half* A_hi = sm + s * 4 * TSZ;
        __half* A_lo = A_hi + TSZ;
        __half* B_hi = A_lo + TSZ;
        __half* B_lo = B_hi + TSZ;
        #pragma unroll
        for (int p = 0; p < 4; p++) {
            int idx = tid + p * 256;
            int row = idx >> 3;
            int cc  = (idx & 7) * 4;
            {
                float4 v = ra[p];
                __half2 h0 = __floats2half2_rn(v.x, v.y);
                __half2 h1 = __floats2half2_rn(v.z, v.w);
                float2 f0 = __half22float2(h0);
                float2 f1 = __half22float2(h1);
                __half2 l0 = __floats2half2_rn(v.x - f0.x, v.y - f0.y);
                __half2 l1 = __floats2half2_rn(v.z - f1.x, v.w - f1.y);
                uint2 hw, lw;
                hw.x = *(uint32_t*)&h0; hw.y = *(uint32_t*)&h1;
                lw.x = *(uint32_t*)&l0; lw.y = *(uint32_t*)&l1;
                *(uint2*)(A_hi + row * TPAD + cc) = hw;
                *(uint2*)(A_lo + row * TPAD + cc) = lw;
            }
            {
                float4 v = rb[p];
                __half2 h0 = __floats2half2_rn(v.x, v.y);
                __half2 h1 = __floats2half2_rn(v.z, v.w);
                float2 f0 = __half22float2(h0);
                float2 f1 = __half22float2(h1);
                __half2 l0 = __floats2half2_rn(v.x - f0.x, v.y - f0.y);
                __half2 l1 = __floats2half2_rn(v.z - f1.x, v.w - f1.y);
                uint2 hw, lw;
                hw.x = *(uint32_t*)&h0; hw.y = *(uint32_t*)&h1;
                lw.x = *(uint32_t*)&l0; lw.y = *(uint32_t*)&l1;
                *(uint2*)(B_hi + row * TPAD + cc) = hw;
                *(uint2*)(B_lo + row * TPAD + cc) = lw;
            }
        }
    };

    auto compute = [&](int s) {
        const uint32_t aHi = smem_u32(sm + s * 4 * TSZ);
        const uint32_t aLo = aHi + TSZ * 2;
        const uint32_t bHi = aLo + TSZ * 2;
        const uint32_t bLo = bHi + TSZ * 2;
        #pragma unroll
        for (int ks = 0; ks < 2; ks++) {
            uint32_t ah[4][4], al[4][4], bh[4][2], bl[4][2];
            const int acol = ks * 16 + (lane >> 4) * 8;
            #pragma unroll
            for (int mi = 0; mi < 4; mi++) {
                int r = wm * 64 + mi * 16 + (lane & 15);
                uint32_t off = (uint32_t)(r * TPAD + acol) * 2;
                ldsm4(ah[mi], aHi + off);
                ldsm4(al[mi], aLo + off);
            }
            const int bcol = ks * 16 + ((lane >> 3) & 1) * 8;
            #pragma unroll
            for (int ni = 0; ni < 4; ni++) {
                int r = wn * 32 + ni * 8 + (lane & 7);
                uint32_t off = (uint32_t)(r * TPAD + bcol) * 2;
                ldsm2(bh[ni], bHi + off);
                ldsm2(bl[ni], bLo + off);
            }
            #pragma unroll
            for (int mi = 0; mi < 4; mi++)
                #pragma unroll
                for (int ni = 0; ni < 4; ni++) {
                    mma16816(acc[mi][ni], ah[mi], bh[ni]);
                    mma16816(acc[mi][ni], ah[mi], bl[ni]);
                    mma16816(acc[mi][ni], al[mi], bh[ni]);
                }
        }
    };

    const int iters = Kd / 32;
    load_regs(0);
    store_tiles(0);
    __syncthreads();
    for (int it = 0; it < iters; it++) {
        const int s = it & 1;
        const bool more = (it + 1 < iters);
        if (more) load_regs(it + 1);
        compute(s);
        if (more) { store_tiles(s ^ 1); __syncthreads(); }
    }

    #pragma unroll
    for (int mi = 0; mi < 4; mi++) {
        const int r0 = m0 + wm * 64 + mi * 16 + g;
        #pragma unroll
        for (int ni = 0; ni < 4; ni++) {
            const int col = n0 + wn * 32 + ni * 8 + tig * 2;
            float2 v0, v1;
            v0.x = acc[mi][ni][0]; v0.y = acc[mi][ni][1];
            v1.x = acc[mi][ni][2]; v1.y = acc[mi][ni][3];
            if (BIAS) {
                float2 bv = *(const float2*)(bias + col);
                v0.x += bv.x; v0.y += bv.y;
                v1.x += bv.x; v1.y += bv.y;
            }
            *(float2*)(C + (size_t)r0 * ldc + col) = v0;
            *(float2*)(C + (size_t)(r0 + 8) * ldc + col) = v1;
        }
    }
}

// ============================================================
// proj transpose: [L,K] -> [K,L]  (z=0: proj_k, z=1: proj_v)
// ============================================================
__global__ __launch_bounds__(256)
void transpose_proj(const float* __restrict__ pk, const float* __restrict__ pv,
                    float* __restrict__ okt, float* __restrict__ ovt)
{
    __shared__ float t[32][33];
    const float* src = blockIdx.z ? pv : pk;
    float* dst       = blockIdx.z ? ovt : okt;
    int k0 = blockIdx.x * 32, l0 = blockIdx.y * 32;
    int tx = threadIdx.x, ty = threadIdx.y;
    #pragma unroll
    for (int i = 0; i < 32; i += 8)
        t[ty + i][tx] = src[(size_t)(l0 + ty + i) * KK + k0 + tx];
    __syncthreads();
    #pragma unroll
    for (int i = 0; i < 32; i += 8)
        dst[(size_t)(k0 + ty + i) * LL + l0 + tx] = t[tx][ty + i];
}

// ============================================================
// add split-K partials
// ============================================================
__global__ __launch_bounds__(256)
void add2(const float* __restrict__ a, const float* __restrict__ b,
          float* __restrict__ o, int n4)
{
    int i = blockIdx.x * blockDim.x + threadIdx.x;
    if (i >= n4) return;
    float4 x = *(const float4*)(a + i * 4);
    float4 y = *(const float4*)(b + i * 4);
    x.x += y.x; x.y += y.y; x.z += y.z; x.w += y.w;
    *(float4*)(o + i * 4) = x;
}

// ============================================================
// MMA attention: CTA = (b, h, 128 q-rows); 8 warps x 16-row tiles.
// Q/K/V staged as hi/lo fp16 split planes in smem.
// S = QK^T (3-MMA split) -> reg softmax -> P repacked in regs (hi/lo)
// -> O = P V (3-MMA split, V via ldmatrix.trans). O scaled by 1/rowsum.
// ============================================================
#define ASTR 72                            // halves per smem row (64+8)
#define AQH 0
#define AQL (128*ASTR)
#define AKH (2*128*ASTR)
#define AKL (AKH + 256*ASTR)
#define AVH (AKL + 256*ASTR)
#define AVL (AVH + 256*ASTR)
#define ATTN_SMEM ((AVL + 256*ASTR) * 2)   // 184320 bytes

__device__ __forceinline__ void split_store8(__half* hi, __half* lo, float4 v) {
    __half2 h0 = __floats2half2_rn(v.x, v.y);
    __half2 h1 = __floats2half2_rn(v.z, v.w);
    float2 f0 = __half22float2(h0);
    float2 f1 = __half22float2(h1);
    __half2 l0 = __floats2half2_rn(v.x - f0.x, v.y - f0.y);
    __half2 l1 = __floats2half2_rn(v.z - f1.x, v.w - f1.y);
    uint2 hw, lw;
    hw.x = *(uint32_t*)&h0; hw.y = *(uint32_t*)&h1;
    lw.x = *(uint32_t*)&l0; lw.y = *(uint32_t*)&l1;
    *(uint2*)hi = hw;
    *(uint2*)lo = lw;
}

__global__ __launch_bounds__(256, 1)
void attn_mma()
{
    extern __shared__ __align__(16) char smc[];
    __half* smh = (__half*)smc;
    const uint32_t base = smem_u32(smc);

    const int b  = blockIdx.z;
    const int h  = blockIdx.y;
    const int l0 = blockIdx.x * 128;
    const int tid  = threadIdx.x;
    const int lane = tid & 31;
    const int wy   = tid >> 5;
    const int g    = lane >> 2;
    const int tig  = lane & 3;

    // ---- fill Q (plain-reshape gather), split to hi/lo ----
    #pragma unroll
    for (int it = 0; it < 8; it++) {
        int idx = tid + it * 256;                 // 0..2047
        int r  = idx >> 4;                        // 0..127
        int dq = (idx & 15) * 4;
        int l  = l0 + r;
        const float* src = g_q + ((size_t)(b * LL) + h * 128 + (l >> 4)) * DD
                               + (l & 15) * DH + dq;
        float4 v = *(const float4*)src;
        split_store8(smh + AQH + r * ASTR + dq, smh + AQL + r * ASTR + dq, v);
    }
    // ---- fill K from g_keys[b][kcol][h*64+dh] ----
    #pragma unroll
    for (int it = 0; it < 16; it++) {
        int idx = tid + it * 256;                 // 0..4095
        int row = idx >> 4;                       // 0..255
        int dq  = (idx & 15) * 4;
        float4 v = *(const float4*)&g_keys[((size_t)b * KK + row) * DD + h * DH + dq];
        split_store8(smh + AKH + row * ASTR + dq, smh + AKL + row * ASTR + dq, v);
    }
    // ---- fill V ----
    #pragma unroll
    for (int it = 0; it < 16; it++) {
        int idx = tid + it * 256;
        int row = idx >> 4;
        int dq  = (idx & 15) * 4;
        float4 v = *(const float4*)&g_vals[((size_t)b * KK + row) * DD + h * DH + dq];
        split_store8(smh + AVH + row * ASTR + dq, smh + AVL + row * ASTR + dq, v);
    }
    __syncthreads();

    const int m0w = wy * 16;

    // ---- A fragments for Q (4 k-steps of 16, hi+lo) ----
    uint32_t qa_h[4][4], qa_l[4][4];
    {
        uint32_t qaddr = base + (uint32_t)((AQH + (m0w + (lane & 15)) * ASTR
                                            + (lane >> 4) * 8) * 2);
        #pragma unroll
        for (int kt = 0; kt < 4; kt++) {
            ldsm4(qa_h[kt], qaddr + kt * 32);
            ldsm4(qa_l[kt], qaddr + kt * 32 + (AQL - AQH) * 2);
        }
    }

    // ---- S = Q K^T : acc[nt][4], nt over 32 8-col tiles ----
    float acc[32][4];
    #pragma unroll
    for (int nt = 0; nt < 32; nt++)
        #pragma unroll
        for (int v = 0; v < 4; v++) acc[nt][v] = 0.f;

    {
        uint32_t kaddr = base + (uint32_t)((AKH + (lane & 7) * ASTR
                                            + (lane >> 3) * 8) * 2);
        #pragma unroll
        for (int nt = 0; nt < 32; nt++) {
            uint32_t a0 = kaddr + (uint32_t)(nt * 8 * ASTR * 2);
            uint32_t kh[8], kl[8];
            ldsm4(kh,     a0);
            ldsm4(kh + 4, a0 + 64);
            ldsm4(kl,     a0 + (AKL - AKH) * 2);
            ldsm4(kl + 4, a0 + (AKL - AKH) * 2 + 64);
            #pragma unroll
            for (int kt = 0; kt < 4; kt++) {
                mma16816(acc[nt], qa_h[kt], kh + kt * 2);
                mma16816(acc[nt], qa_h[kt], kl + kt * 2);
                mma16816(acc[nt], qa_l[kt], kh + kt * 2);
            }
        }
    }

    // ---- softmax over 256 cols (rows g and g+8) ----
    const float SC = 0.125f;   // 64^-0.5
    float mx0 = -1e30f, mx1 = -1e30f;
    #pragma unroll
    for (int nt = 0; nt < 32; nt++) {
        mx0 = fmaxf(mx0, fmaxf(acc[nt][0], acc[nt][1]));
        mx1 = fmaxf(mx1, fmaxf(acc[nt][2], acc[nt][3]));
    }
    #pragma unroll
    for (int o = 1; o <= 2; o <<= 1) {
        mx0 = fmaxf(mx0, __shfl_xor_sync(0xffffffffu, mx0, o));
        mx1 = fmaxf(mx1, __shfl_xor_sync(0xffffffffu, mx1, o));
    }
    const float b0 = mx0 * SC, b1 = mx1 * SC;
    float s0 = 0.f, s1 = 0.f;
    #pragma unroll
    for (int nt = 0; nt < 32; nt++) {
        acc[nt][0] = __expf(acc[nt][0] * SC - b0);
        acc[nt][1] = __expf(acc[nt][1] * SC - b0);
        acc[nt][2] = __expf(acc[nt][2] * SC - b1);
        acc[nt][3] = __expf(acc[nt][3] * SC - b1);
        s0 += acc[nt][0] + acc[nt][1];
        s1 += acc[nt][2] + acc[nt][3];
    }
    #pragma unroll
    for (int o = 1; o <= 2; o <<= 1) {
        s0 += __shfl_xor_sync(0xffffffffu, s0, o);
        s1 += __shfl_xor_sync(0xffffffffu, s1, o);
    }
    const float inv0 = 1.f / s0, inv1 = 1.f / s1;

    // ---- O = P V (P from regs; V via ldmatrix.trans, hi/lo split) ----
    float oac[8][4];
    #pragma unroll
    for (int nj = 0; nj < 8; nj++)
        #pragma unroll
        for (int v = 0; v < 4; v++) oac[nj][v] = 0.f;

    {
        uint32_t vaddr = base + (uint32_t)((AVH + (lane & 15) * ASTR) * 2);
        #pragma unroll
        for (int kt = 0; kt < 16; kt++) {
            // pack P frag (hi/lo) from acc[2kt], acc[2kt+1]
            uint32_t ph[4], pl[4];
            #pragma unroll
            for (int half_ = 0; half_ < 2; half_++) {
                const float* c = acc[2 * kt + half_];
                __half2 h0 = __floats2half2_rn(c[0], c[1]);
                __half2 h1 = __floats2half2_rn(c[2], c[3]);
                float2 f0 = __half22float2(h0);
                float2 f1 = __half22float2(h1);
                __half2 e0 = __floats2half2_rn(c[0] - f0.x, c[1] - f0.y);
                __half2 e1 = __floats2half2_rn(c[2] - f1.x, c[3] - f1.y);
                ph[half_ * 2 + 0] = *(uint32_t*)&h0;
                ph[half_ * 2 + 1] = *(uint32_t*)&h1;
                pl[half_ * 2 + 0] = *(uint32_t*)&e0;
                pl[half_ * 2 + 1] = *(uint32_t*)&e1;
            }
            uint32_t rowb = vaddr + (uint32_t)(kt * 16 * ASTR * 2);
            #pragma unroll
            for (int nj = 0; nj < 8; nj++) {
                uint32_t vh[2], vl[2];
                ldsm2t(vh, rowb + nj * 16);
                ldsm2t(vl, rowb + nj * 16 + (AVL - AVH) * 2);
                mma16816(oac[nj], ph, vh);
                mma16816(oac[nj], ph, vl);
                mma16816(oac[nj], pl, vh);
            }
        }
    }

    // ---- epilogue: scale by 1/rowsum, store ctx f32 ----
    {
        const int r0 = l0 + m0w + g;
        const size_t orow = ((size_t)(b * LL) + r0) * DD + h * DH;
        #pragma unroll
        for (int nj = 0; nj < 8; nj++) {
            float2 v0, v1;
            v0.x = oac[nj][0] * inv0; v0.y = oac[nj][1] * inv0;
            v1.x = oac[nj][2] * inv1; v1.y = oac[nj][3] * inv1;
            *(float2*)&g_ctx[orow + nj * 8 + tig * 2] = v0;
            *(float2*)&g_ctx[orow + (size_t)8 * DD + nj * 8 + tig * 2] = v1;
        }
    }
}

// ============================================================
extern "C" void kernel_launch(void* const* d_in, const int* in_sizes, int n_in,
                              void* d_out, int out_size)
{
    const float* x      = (const float*)d_in[0];
    const float* Wq     = (const float*)d_in[1];
    const float* Wk     = (const float*)d_in[2];
    const float* Wv     = (const float*)d_in[3];
    const float* proj_k = (const float*)d_in[4];
    const float* proj_v = (const float*)d_in[5];
    const float* Wo     = (const float*)d_in[6];
    const float* bo     = (const float*)d_in[7];
    float* out = (float*)d_out;

    float *q, *xkt, *xvt, *projkt, *projvt, *keys2, *vals2, *keys, *vals, *ctx;
    cudaGetSymbolAddress((void**)&q,      g_q);
    cudaGetSymbolAddress((void**)&xkt,    g_xkt);
    cudaGetSymbolAddress((void**)&xvt,    g_xvt);
    cudaGetSymbolAddress((void**)&projkt, g_projkt);
    cudaGetSymbolAddress((void**)&projvt, g_projvt);
    cudaGetSymbolAddress((void**)&keys2,  g_keys2);
    cudaGetSymbolAddress((void**)&vals2,  g_vals2);
    cudaGetSymbolAddress((void**)&keys,   g_keys);
    cudaGetSymbolAddress((void**)&vals,   g_vals);
    cudaGetSymbolAddress((void**)&ctx,    g_ctx);

    cudaFuncSetAttribute(gemm_fp16x2<false>, cudaFuncAttributeMaxDynamicSharedMemorySize, GEMM_SMEM);
    cudaFuncSetAttribute(gemm_fp16x2<true>,  cudaFuncAttributeMaxDynamicSharedMemorySize, GEMM_SMEM);
    cudaFuncSetAttribute(attn_mma, cudaFuncAttributeMaxDynamicSharedMemorySize, ATTN_SMEM);

    // proj_k / proj_v -> transposed [K,L]
    transpose_proj<<<dim3(KK/32, LL/32, 2), dim3(32, 8)>>>(proj_k, proj_v, projkt, projvt);

    // q = x @ Wq^T
    gemm_fp16x2<false><<<dim3(DD/128, MROWS/128, 1), 256, GEMM_SMEM>>>(
        x, 0, DD, Wq, 0, DD, q, 0, 0, DD, nullptr, DD, 1);

    // xkt[b] = Wk x_b^T : [D, L]
    gemm_fp16x2<false><<<dim3(LL/128, DD/128, BB), 256, GEMM_SMEM>>>(
        Wk, 0, DD, x, (long)LL*DD, DD, xkt, (long)DD*LL, 0, LL, nullptr, DD, 1);

    // xvt[b]
    gemm_fp16x2<false><<<dim3(LL/128, DD/128, BB), 256, GEMM_SMEM>>>(
        Wv, 0, DD, x, (long)LL*DD, DD, xvt, (long)DD*LL, 0, LL, nullptr, DD, 1);

    // keys partials [zs][b][K,D] = projkt x xkt^T  (split-K over L)
    gemm_fp16x2<false><<<dim3(DD/128, KK/128, BB*2), 256, GEMM_SMEM>>>(
        projkt, 0, LL, xkt, (long)DD*LL, LL,
        keys2, (long)KK*DD, (long)BB*KK*DD, DD, nullptr, LL/2, 2);

    // vals partials [zs][b][K,D]
    gemm_fp16x2<false><<<dim3(DD/128, KK/128, BB*2), 256, GEMM_SMEM>>>(
        projvt, 0, LL, xvt, (long)DD*LL, LL,
        vals2, (long)KK*DD, (long)BB*KK*DD, DD, nullptr, LL/2, 2);

    add2<<<(BB*KK*DD/4 + 255)/256, 256>>>(keys2, keys2 + (size_t)BB*KK*DD, keys, BB*KK*DD/4);
    add2<<<(BB*KK*DD/4 + 255)/256, 256>>>(vals2, vals2 + (size_t)BB*KK*DD, vals, BB*KK*DD/4);

    // MMA attention
    attn_mma<<<dim3(LL/128, HH, BB), 256, ATTN_SMEM>>>();

    // out = ctx @ Wo^T + bo
    gemm_fp16x2<true><<<dim3(DD/128, MROWS/128, 1), 256, GEMM_SMEM>>>(
        ctx, 0, DD, Wo, 0, DD, out, 0, 0, DD, bo, DD, 1);
}

// round 7
// speedup vs baseline: 1.4742x; 1.0309x over previous
#include <cuda_runtime.h>
#include <cuda_fp16.h>
#include <cstdint>
#include <math.h>

#define BB 4
#define LL 2048
#define DD 1024
#define HH 16
#define KK 256
#define DH 64
#define MROWS (BB*LL)   // 8192

// ---- scratch (device globals; no runtime allocation allowed) ----
__device__ float g_q[BB*LL*DD];        // x @ Wq^T            [B,L,D]
__device__ float g_xkt[BB*DD*LL];      // (x @ Wk^T)^T        [B,D,L]
__device__ float g_xvt[BB*DD*LL];      // (x @ Wv^T)^T        [B,D,L]
__device__ float g_projkt[KK*LL];      // proj_k^T            [K,L]
__device__ float g_projvt[KK*LL];      // proj_v^T            [K,L]
__device__ float g_keys2[2*BB*KK*DD];  // split-K partials
__device__ float g_vals2[2*BB*KK*DD];
__device__ float g_keys[BB*KK*DD];     // keys [B,K,D]
__device__ float g_vals[BB*KK*DD];     // vals [B,K,D]
__device__ float g_ctx[BB*LL*DD];      // attention out       [B,L,D]

// ============================================================
// mma.sync helpers (baseline PTX, works on compute_103)
// ============================================================
__device__ __forceinline__ uint32_t smem_u32(const void* p) {
    uint32_t a;
    asm("{ .reg .u64 t; cvta.to.shared.u64 t, %1; cvt.u32.u64 %0, t; }"
        : "=r"(a) : "l"(p));
    return a;
}
__device__ __forceinline__ void ldsm4(uint32_t* r, uint32_t addr) {
    asm volatile("ldmatrix.sync.aligned.m8n8.x4.shared.b16 {%0,%1,%2,%3}, [%4];"
        : "=r"(r[0]), "=r"(r[1]), "=r"(r[2]), "=r"(r[3]) : "r"(addr));
}
__device__ __forceinline__ void ldsm2(uint32_t* r, uint32_t addr) {
    asm volatile("ldmatrix.sync.aligned.m8n8.x2.shared.b16 {%0,%1}, [%2];"
        : "=r"(r[0]), "=r"(r[1]) : "r"(addr));
}
__device__ __forceinline__ void ldsm2t(uint32_t* r, uint32_t addr) {
    asm volatile("ldmatrix.sync.aligned.m8n8.x2.trans.shared.b16 {%0,%1}, [%2];"
        : "=r"(r[0]), "=r"(r[1]) : "r"(addr));
}
__device__ __forceinline__ void mma16816(float* c, const uint32_t* a, const uint32_t* b) {
    asm volatile(
        "mma.sync.aligned.m16n8k16.row.col.f32.f16.f16.f32 "
        "{%0,%1,%2,%3}, {%4,%5,%6,%7}, {%8,%9}, {%0,%1,%2,%3};"
        : "+f"(c[0]), "+f"(c[1]), "+f"(c[2]), "+f"(c[3])
        : "r"(a[0]), "r"(a[1]), "r"(a[2]), "r"(a[3]), "r"(b[0]), "r"(b[1]));
}
#define BAR_SYNC(id)   asm volatile("bar.sync %0, 384;"   :: "r"(id) : "memory")
#define BAR_ARRIVE(id) asm volatile("bar.arrive %0, 384;" :: "r"(id) : "memory")

// ============================================================
// Warp-specialized split-fp16 NT-GEMM:
// C[m,n] = sum_k A[m,k]*B[n,k]  (+bias[n]); f32 in, split inline.
// 384 threads: warps 0-7 consumers (ldmatrix+MMA only, warp tile 64x32),
// warps 8-11 producers (LDG f32 -> hi/lo convert -> STS).
// CTA tile 128x128, BK=32, 3-stage smem ring, named-barrier sync.
// ============================================================
#define TPAD 40
#define TSZ  (128*TPAD)
#define NSTG 3
#define GEMM_SMEM (NSTG*4*TSZ*2)    // 122880

template<bool BIAS>
__global__ __launch_bounds__(384, 1)
void gemm_ws(const float* __restrict__ A, long Ab, int lda,
             const float* __restrict__ B, long Bb, int ldb,
             float* __restrict__ C, long Cb, long Cs, int ldc,
             const float* __restrict__ bias, int Kd, int ksp)
{
    extern __shared__ __align__(16) char smc[];
    __half* sm = (__half*)smc;

    const int tid  = threadIdx.x;
    const int lane = tid & 31;
    const int wid  = tid >> 5;

    const int zb = blockIdx.z / ksp;
    const int zs = blockIdx.z % ksp;
    A += (size_t)zb * Ab + (size_t)zs * Kd;
    B += (size_t)zb * Bb + (size_t)zs * Kd;
    C += (size_t)zb * Cb + (size_t)zs * Cs;
    const int m0 = blockIdx.y * 128;
    const int n0 = blockIdx.x * 128;
    const int iters = Kd / 32;

    if (wid >= 8) {
        // ================= producers (4 warps, 128 threads) =================
        const int ptid = tid - 256;
        const float* Aip = A + (size_t)m0 * lda;
        const float* Bip = B + (size_t)n0 * ldb;

        for (int it = 0; it < iters; it++) {
            const int s = it % NSTG;
            if (it >= NSTG) BAR_SYNC(4 + s);          // EMPTY(s)
            const int k0 = it * 32;

            float4 ra[8], rb[8];
            #pragma unroll
            for (int p = 0; p < 8; p++) {
                int idx = ptid + p * 128;
                int row = idx >> 3;
                int cc  = (idx & 7) * 4;
                ra[p] = *(const float4*)(Aip + (size_t)row * lda + k0 + cc);
                rb[p] = *(const float4*)(Bip + (size_t)row * ldb + k0 + cc);
            }
            __half* A_hi = sm + s * 4 * TSZ;
            __half* A_lo = A_hi + TSZ;
            __half* B_hi = A_lo + TSZ;
            __half* B_lo = B_hi + TSZ;
            #pragma unroll
            for (int p = 0; p < 8; p++) {
                int idx = ptid + p * 128;
                int row = idx >> 3;
                int cc  = (idx & 7) * 4;
                {
                    float4 v = ra[p];
                    __half2 h0 = __floats2half2_rn(v.x, v.y);
                    __half2 h1 = __floats2half2_rn(v.z, v.w);
                    float2 f0 = __half22float2(h0);
                    float2 f1 = __half22float2(h1);
                    __half2 l0 = __floats2half2_rn(v.x - f0.x, v.y - f0.y);
                    __half2 l1 = __floats2half2_rn(v.z - f1.x, v.w - f1.y);
                    uint2 hw, lw;
                    hw.x = *(uint32_t*)&h0; hw.y = *(uint32_t*)&h1;
                    lw.x = *(uint32_t*)&l0; lw.y = *(uint32_t*)&l1;
                    *(uint2*)(A_hi + row * TPAD + cc) = hw;
                    *(uint2*)(A_lo + row * TPAD + cc) = lw;
                }
                {
                    float4 v = rb[p];
                    __half2 h0 = __floats2half2_rn(v.x, v.y);
                    __half2 h1 = __floats2half2_rn(v.z, v.w);
                    float2 f0 = __half22float2(h0);
                    float2 f1 = __half22float2(h1);
                    __half2 l0 = __floats2half2_rn(v.x - f0.x, v.y - f0.y);
                    __half2 l1 = __floats2half2_rn(v.z - f1.x, v.w - f1.y);
                    uint2 hw, lw;
                    hw.x = *(uint32_t*)&h0; hw.y = *(uint32_t*)&h1;
                    lw.x = *(uint32_t*)&l0; lw.y = *(uint32_t*)&l1;
                    *(uint2*)(B_hi + row * TPAD + cc) = hw;
                    *(uint2*)(B_lo + row * TPAD + cc) = lw;
                }
            }
            BAR_ARRIVE(1 + s);                        // FULL(s)
        }
    } else {
        // ================= consumers (8 warps) =================
        const int wm = wid >> 2;
        const int wn = wid & 3;
        const int g  = lane >> 2;
        const int tig = lane & 3;

        float acc[4][4][4];
        #pragma unroll
        for (int i = 0; i < 4; i++)
            #pragma unroll
            for (int j = 0; j < 4; j++)
                #pragma unroll
                for (int v = 0; v < 4; v++) acc[i][j][v] = 0.f;

        for (int it = 0; it < iters; it++) {
            const int s = it % NSTG;
            BAR_SYNC(1 + s);                          // FULL(s)

            const uint32_t aHi = smem_u32(sm + s * 4 * TSZ);
            const uint32_t aLo = aHi + TSZ * 2;
            const uint32_t bHi = aLo + TSZ * 2;
            const uint32_t bLo = bHi + TSZ * 2;
            #pragma unroll
            for (int ks = 0; ks < 2; ks++) {
                uint32_t ah[4][4], al[4][4], bh[4][2], bl[4][2];
                const int acol = ks * 16 + (lane >> 4) * 8;
                #pragma unroll
                for (int mi = 0; mi < 4; mi++) {
                    int r = wm * 64 + mi * 16 + (lane & 15);
                    uint32_t off = (uint32_t)(r * TPAD + acol) * 2;
                    ldsm4(ah[mi], aHi + off);
                    ldsm4(al[mi], aLo + off);
                }
                const int bcol = ks * 16 + ((lane >> 3) & 1) * 8;
                #pragma unroll
                for (int ni = 0; ni < 4; ni++) {
                    int r = wn * 32 + ni * 8 + (lane & 7);
                    uint32_t off = (uint32_t)(r * TPAD + bcol) * 2;
                    ldsm2(bh[ni], bHi + off);
                    ldsm2(bl[ni], bLo + off);
                }
                #pragma unroll
                for (int mi = 0; mi < 4; mi++)
                    #pragma unroll
                    for (int ni = 0; ni < 4; ni++) {
                        mma16816(acc[mi][ni], ah[mi], bh[ni]);
                        mma16816(acc[mi][ni], ah[mi], bl[ni]);
                        mma16816(acc[mi][ni], al[mi], bh[ni]);
                    }
            }
            BAR_ARRIVE(4 + s);                        // EMPTY(s)
        }

        // ---- epilogue ----
        #pragma unroll
        for (int mi = 0; mi < 4; mi++) {
            const int r0 = m0 + wm * 64 + mi * 16 + g;
            #pragma unroll
            for (int ni = 0; ni < 4; ni++) {
                const int col = n0 + wn * 32 + ni * 8 + tig * 2;
                float2 v0, v1;
                v0.x = acc[mi][ni][0]; v0.y = acc[mi][ni][1];
                v1.x = acc[mi][ni][2]; v1.y = acc[mi][ni][3];
                if (BIAS) {
                    float2 bv = *(const float2*)(bias + col);
                    v0.x += bv.x; v0.y += bv.y;
                    v1.x += bv.x; v1.y += bv.y;
                }
                *(float2*)(C + (size_t)r0 * ldc + col) = v0;
                *(float2*)(C + (size_t)(r0 + 8) * ldc + col) = v1;
            }
        }
    }
}

// ============================================================
// proj transpose: [L,K] -> [K,L]  (z=0: proj_k, z=1: proj_v)
// ============================================================
__global__ __launch_bounds__(256)
void transpose_proj(const float* __restrict__ pk, const float* __restrict__ pv,
                    float* __restrict__ okt, float* __restrict__ ovt)
{
    __shared__ float t[32][33];
    const float* src = blockIdx.z ? pv : pk;
    float* dst       = blockIdx.z ? ovt : okt;
    int k0 = blockIdx.x * 32, l0 = blockIdx.y * 32;
    int tx = threadIdx.x, ty = threadIdx.y;
    #pragma unroll
    for (int i = 0; i < 32; i += 8)
        t[ty + i][tx] = src[(size_t)(l0 + ty + i) * KK + k0 + tx];
    __syncthreads();
    #pragma unroll
    for (int i = 0; i < 32; i += 8)
        dst[(size_t)(k0 + ty + i) * LL + l0 + tx] = t[tx][ty + i];
}

// ============================================================
// add split-K partials
// ============================================================
__global__ __launch_bounds__(256)
void add2(const float* __restrict__ a, const float* __restrict__ b,
          float* __restrict__ o, int n4)
{
    int i = blockIdx.x * blockDim.x + threadIdx.x;
    if (i >= n4) return;
    float4 x = *(const float4*)(a + i * 4);
    float4 y = *(const float4*)(b + i * 4);
    x.x += y.x; x.y += y.y; x.z += y.z; x.w += y.w;
    *(float4*)(o + i * 4) = x;
}

// ============================================================
// MMA attention (R6-verified): CTA = (b, h, 128 q-rows); 8 warps.
// ============================================================
#define ASTR 72
#define AQH 0
#define AQL (128*ASTR)
#define AKH (2*128*ASTR)
#define AKL (AKH + 256*ASTR)
#define AVH (AKL + 256*ASTR)
#define AVL (AVH + 256*ASTR)
#define ATTN_SMEM ((AVL + 256*ASTR) * 2)   // 184320 bytes

__device__ __forceinline__ void split_store8(__half* hi, __half* lo, float4 v) {
    __half2 h0 = __floats2half2_rn(v.x, v.y);
    __half2 h1 = __floats2half2_rn(v.z, v.w);
    float2 f0 = __half22float2(h0);
    float2 f1 = __half22float2(h1);
    __half2 l0 = __floats2half2_rn(v.x - f0.x, v.y - f0.y);
    __half2 l1 = __floats2half2_rn(v.z - f1.x, v.w - f1.y);
    uint2 hw, lw;
    hw.x = *(uint32_t*)&h0; hw.y = *(uint32_t*)&h1;
    lw.x = *(uint32_t*)&l0; lw.y = *(uint32_t*)&l1;
    *(uint2*)hi = hw;
    *(uint2*)lo = lw;
}

__global__ __launch_bounds__(256, 1)
void attn_mma()
{
    extern __shared__ __align__(16) char smc[];
    __half* smh = (__half*)smc;
    const uint32_t base = smem_u32(smc);

    const int b  = blockIdx.z;
    const int h  = blockIdx.y;
    const int l0 = blockIdx.x * 128;
    const int tid  = threadIdx.x;
    const int lane = tid & 31;
    const int wy   = tid >> 5;
    const int g    = lane >> 2;
    const int tig  = lane & 3;

    #pragma unroll
    for (int it = 0; it < 8; it++) {
        int idx = tid + it * 256;
        int r  = idx >> 4;
        int dq = (idx & 15) * 4;
        int l  = l0 + r;
        const float* src = g_q + ((size_t)(b * LL) + h * 128 + (l >> 4)) * DD
                               + (l & 15) * DH + dq;
        float4 v = *(const float4*)src;
        split_store8(smh + AQH + r * ASTR + dq, smh + AQL + r * ASTR + dq, v);
    }
    #pragma unroll
    for (int it = 0; it < 16; it++) {
        int idx = tid + it * 256;
        int row = idx >> 4;
        int dq  = (idx & 15) * 4;
        float4 v = *(const float4*)&g_keys[((size_t)b * KK + row) * DD + h * DH + dq];
        split_store8(smh + AKH + row * ASTR + dq, smh + AKL + row * ASTR + dq, v);
    }
    #pragma unroll
    for (int it = 0; it < 16; it++) {
        int idx = tid + it * 256;
        int row = idx >> 4;
        int dq  = (idx & 15) * 4;
        float4 v = *(const float4*)&g_vals[((size_t)b * KK + row) * DD + h * DH + dq];
        split_store8(smh + AVH + row * ASTR + dq, smh + AVL + row * ASTR + dq, v);
    }
    __syncthreads();

    const int m0w = wy * 16;

    uint32_t qa_h[4][4], qa_l[4][4];
    {
        uint32_t qaddr = base + (uint32_t)((AQH + (m0w + (lane & 15)) * ASTR
                                            + (lane >> 4) * 8) * 2);
        #pragma unroll
        for (int kt = 0; kt < 4; kt++) {
            ldsm4(qa_h[kt], qaddr + kt * 32);
            ldsm4(qa_l[kt], qaddr + kt * 32 + (AQL - AQH) * 2);
        }
    }

    float acc[32][4];
    #pragma unroll
    for (int nt = 0; nt < 32; nt++)
        #pragma unroll
        for (int v = 0; v < 4; v++) acc[nt][v] = 0.f;

    {
        uint32_t kaddr = base + (uint32_t)((AKH + (lane & 7) * ASTR
                                            + (lane >> 3) * 8) * 2);
        #pragma unroll
        for (int nt = 0; nt < 32; nt++) {
            uint32_t a0 = kaddr + (uint32_t)(nt * 8 * ASTR * 2);
            uint32_t kh[8], kl[8];
            ldsm4(kh,     a0);
            ldsm4(kh + 4, a0 + 64);
            ldsm4(kl,     a0 + (AKL - AKH) * 2);
            ldsm4(kl + 4, a0 + (AKL - AKH) * 2 + 64);
            #pragma unroll
            for (int kt = 0; kt < 4; kt++) {
                mma16816(acc[nt], qa_h[kt], kh + kt * 2);
                mma16816(acc[nt], qa_h[kt], kl + kt * 2);
                mma16816(acc[nt], qa_l[kt], kh + kt * 2);
            }
        }
    }

    const float SC = 0.125f;
    float mx0 = -1e30f, mx1 = -1e30f;
    #pragma unroll
    for (int nt = 0; nt < 32; nt++) {
        mx0 = fmaxf(mx0, fmaxf(acc[nt][0], acc[nt][1]));
        mx1 = fmaxf(mx1, fmaxf(acc[nt][2], acc[nt][3]));
    }
    #pragma unroll
    for (int o = 1; o <= 2; o <<= 1) {
        mx0 = fmaxf(mx0, __shfl_xor_sync(0xffffffffu, mx0, o));
        mx1 = fmaxf(mx1, __shfl_xor_sync(0xffffffffu, mx1, o));
    }
    const float b0 = mx0 * SC, b1 = mx1 * SC;
    float s0 = 0.f, s1 = 0.f;
    #pragma unroll
    for (int nt = 0; nt < 32; nt++) {
        acc[nt][0] = __expf(acc[nt][0] * SC - b0);
        acc[nt][1] = __expf(acc[nt][1] * SC - b0);
        acc[nt][2] = __expf(acc[nt][2] * SC - b1);
        acc[nt][3] = __expf(acc[nt][3] * SC - b1);
        s0 += acc[nt][0] + acc[nt][1];
        s1 += acc[nt][2] + acc[nt][3];
    }
    #pragma unroll
    for (int o = 1; o <= 2; o <<= 1) {
        s0 += __shfl_xor_sync(0xffffffffu, s0, o);
        s1 += __shfl_xor_sync(0xffffffffu, s1, o);
    }
    const float inv0 = 1.f / s0, inv1 = 1.f / s1;

    float oac[8][4];
    #pragma unroll
    for (int nj = 0; nj < 8; nj++)
        #pragma unroll
        for (int v = 0; v < 4; v++) oac[nj][v] = 0.f;

    {
        uint32_t vaddr = base + (uint32_t)((AVH + (lane & 15) * ASTR) * 2);
        #pragma unroll
        for (int kt = 0; kt < 16; kt++) {
            uint32_t ph[4], pl[4];
            #pragma unroll
            for (int half_ = 0; half_ < 2; half_++) {
                const float* c = acc[2 * kt + half_];
                __half2 h0 = __floats2half2_rn(c[0], c[1]);
                __half2 h1 = __floats2half2_rn(c[2], c[3]);
                float2 f0 = __half22float2(h0);
                float2 f1 = __half22float2(h1);
                __half2 e0 = __floats2half2_rn(c[0] - f0.x, c[1] - f0.y);
                __half2 e1 = __floats2half2_rn(c[2] - f1.x, c[3] - f1.y);
                ph[half_ * 2 + 0] = *(uint32_t*)&h0;
                ph[half_ * 2 + 1] = *(uint32_t*)&h1;
                pl[half_ * 2 + 0] = *(uint32_t*)&e0;
                pl[half_ * 2 + 1] = *(uint32_t*)&e1;
            }
            uint32_t rowb = vaddr + (uint32_t)(kt * 16 * ASTR * 2);
            #pragma unroll
            for (int nj = 0; nj < 8; nj++) {
                uint32_t vh[2], vl[2];
                ldsm2t(vh, rowb + nj * 16);
                ldsm2t(vl, rowb + nj * 16 + (AVL - AVH) * 2);
                mma16816(oac[nj], ph, vh);
                mma16816(oac[nj], ph, vl);
                mma16816(oac[nj], pl, vh);
            }
        }
    }

    {
        const int r0 = l0 + m0w + g;
        const size_t orow = ((size_t)(b * LL) + r0) * DD + h * DH;
        #pragma unroll
        for (int nj = 0; nj < 8; nj++) {
            float2 v0, v1;
            v0.x = oac[nj][0] * inv0; v0.y = oac[nj][1] * inv0;
            v1.x = oac[nj][2] * inv1; v1.y = oac[nj][3] * inv1;
            *(float2*)&g_ctx[orow + nj * 8 + tig * 2] = v0;
            *(float2*)&g_ctx[orow + (size_t)8 * DD + nj * 8 + tig * 2] = v1;
        }
    }
}

// ============================================================
extern "C" void kernel_launch(void* const* d_in, const int* in_sizes, int n_in,
                              void* d_out, int out_size)
{
    const float* x      = (const float*)d_in[0];
    const float* Wq     = (const float*)d_in[1];
    const float* Wk     = (const float*)d_in[2];
    const float* Wv     = (const float*)d_in[3];
    const float* proj_k = (const float*)d_in[4];
    const float* proj_v = (const float*)d_in[5];
    const float* Wo     = (const float*)d_in[6];
    const float* bo     = (const float*)d_in[7];
    float* out = (float*)d_out;

    float *q, *xkt, *xvt, *projkt, *projvt, *keys2, *vals2, *keys, *vals, *ctx;
    cudaGetSymbolAddress((void**)&q,      g_q);
    cudaGetSymbolAddress((void**)&xkt,    g_xkt);
    cudaGetSymbolAddress((void**)&xvt,    g_xvt);
    cudaGetSymbolAddress((void**)&projkt, g_projkt);
    cudaGetSymbolAddress((void**)&projvt, g_projvt);
    cudaGetSymbolAddress((void**)&keys2,  g_keys2);
    cudaGetSymbolAddress((void**)&vals2,  g_vals2);
    cudaGetSymbolAddress((void**)&keys,   g_keys);
    cudaGetSymbolAddress((void**)&vals,   g_vals);
    cudaGetSymbolAddress((void**)&ctx,    g_ctx);

    cudaFuncSetAttribute(gemm_ws<false>, cudaFuncAttributeMaxDynamicSharedMemorySize, GEMM_SMEM);
    cudaFuncSetAttribute(gemm_ws<true>,  cudaFuncAttributeMaxDynamicSharedMemorySize, GEMM_SMEM);
    cudaFuncSetAttribute(attn_mma, cudaFuncAttributeMaxDynamicSharedMemorySize, ATTN_SMEM);

    // proj_k / proj_v -> transposed [K,L]
    transpose_proj<<<dim3(KK/32, LL/32, 2), dim3(32, 8)>>>(proj_k, proj_v, projkt, projvt);

    // q = x @ Wq^T
    gemm_ws<false><<<dim3(DD/128, MROWS/128, 1), 384, GEMM_SMEM>>>(
        x, 0, DD, Wq, 0, DD, q, 0, 0, DD, nullptr, DD, 1);

    // xkt[b] = Wk x_b^T : [D, L]
    gemm_ws<false><<<dim3(LL/128, DD/128, BB), 384, GEMM_SMEM>>>(
        Wk, 0, DD, x, (long)LL*DD, DD, xkt, (long)DD*LL, 0, LL, nullptr, DD, 1);

    // xvt[b]
    gemm_ws<false><<<dim3(LL/128, DD/128, BB), 384, GEMM_SMEM>>>(
        Wv, 0, DD, x, (long)LL*DD, DD, xvt, (long)DD*LL, 0, LL, nullptr, DD, 1);

    // keys partials [zs][b][K,D] = projkt x xkt^T  (split-K over L)
    gemm_ws<false><<<dim3(DD/128, KK/128, BB*2), 384, GEMM_SMEM>>>(
        projkt, 0, LL, xkt, (long)DD*LL, LL,
        keys2, (long)KK*DD, (long)BB*KK*DD, DD, nullptr, LL/2, 2);

    // vals partials [zs][b][K,D]
    gemm_ws<false><<<dim3(DD/128, KK/128, BB*2), 384, GEMM_SMEM>>>(
        projvt, 0, LL, xvt, (long)DD*LL, LL,
        vals2, (long)KK*DD, (long)BB*KK*DD, DD, nullptr, LL/2, 2);

    add2<<<(BB*KK*DD/4 + 255)/256, 256>>>(keys2, keys2 + (size_t)BB*KK*DD, keys, BB*KK*DD/4);
    add2<<<(BB*KK*DD/4 + 255)/256, 256>>>(vals2, vals2 + (size_t)BB*KK*DD, vals, BB*KK*DD/4);

    // MMA attention
    attn_mma<<<dim3(LL/128, HH, BB), 256, ATTN_SMEM>>>();

    // out = ctx @ Wo^T + bo
    gemm_ws<true><<<dim3(DD/128, MROWS/128, 1), 384, GEMM_SMEM>>>(
        ctx, 0, DD, Wo, 0, DD, out, 0, 0, DD, bo, DD, 1);
}

// round 8
// speedup vs baseline: 1.4835x; 1.0063x over previous
#include <cuda_runtime.h>
#include <cuda_fp16.h>
#include <cstdint>
#include <math.h>

#define BB 4
#define LL 2048
#define DD 1024
#define HH 16
#define KK 256
#define DH 64
#define MROWS (BB*LL)   // 8192

// ---- scratch (device globals; no runtime allocation allowed) ----
__device__ float g_q[BB*LL*DD];        // x @ Wq^T            [B,L,D]
__device__ float g_xkt[BB*DD*LL];      // (x @ Wk^T)^T        [B,D,L]
__device__ float g_xvt[BB*DD*LL];      // (x @ Wv^T)^T        [B,D,L]
__device__ float g_projkt[KK*LL];      // proj_k^T            [K,L]
__device__ float g_projvt[KK*LL];      // proj_v^T            [K,L]
__device__ float g_keys2[2*BB*KK*DD];  // split-K partials
__device__ float g_vals2[2*BB*KK*DD];
__device__ float g_keys[BB*KK*DD];     // keys [B,K,D]
__device__ float g_vals[BB*KK*DD];     // vals [B,K,D]
__device__ float g_ctx[BB*LL*DD];      // attention out       [B,L,D]

// ============================================================
// helpers
// ============================================================
__device__ __forceinline__ uint32_t smem_u32(const void* p) {
    uint32_t a;
    asm("{ .reg .u64 t; cvta.to.shared.u64 t, %1; cvt.u32.u64 %0, t; }"
        : "=r"(a) : "l"(p));
    return a;
}
__device__ __forceinline__ void ldsm4(uint32_t* r, uint32_t addr) {
    asm volatile("ldmatrix.sync.aligned.m8n8.x4.shared.b16 {%0,%1,%2,%3}, [%4];"
        : "=r"(r[0]), "=r"(r[1]), "=r"(r[2]), "=r"(r[3]) : "r"(addr));
}
__device__ __forceinline__ void ldsm2(uint32_t* r, uint32_t addr) {
    asm volatile("ldmatrix.sync.aligned.m8n8.x2.shared.b16 {%0,%1}, [%2];"
        : "=r"(r[0]), "=r"(r[1]) : "r"(addr));
}
__device__ __forceinline__ void ldsm2t(uint32_t* r, uint32_t addr) {
    asm volatile("ldmatrix.sync.aligned.m8n8.x2.trans.shared.b16 {%0,%1}, [%2];"
        : "=r"(r[0]), "=r"(r[1]) : "r"(addr));
}
__device__ __forceinline__ void mma16816(float* c, const uint32_t* a, const uint32_t* b) {
    asm volatile(
        "mma.sync.aligned.m16n8k16.row.col.f32.f16.f16.f32 "
        "{%0,%1,%2,%3}, {%4,%5,%6,%7}, {%8,%9}, {%0,%1,%2,%3};"
        : "+f"(c[0]), "+f"(c[1]), "+f"(c[2]), "+f"(c[3])
        : "r"(a[0]), "r"(a[1]), "r"(a[2]), "r"(a[3]), "r"(b[0]), "r"(b[1]));
}
#define BAR_SYNC(id)   asm volatile("bar.sync %0, 384;"   :: "r"(id) : "memory")
#define BAR_ARRIVE(id) asm volatile("bar.arrive %0, 384;" :: "r"(id) : "memory")

// split 8 f32 -> 16B hi chunk + 16B lo chunk
__device__ __forceinline__ void cvt_split16(float4 a, float4 b, uint4& hi, uint4& lo) {
    __half2 h0 = __floats2half2_rn(a.x, a.y);
    __half2 h1 = __floats2half2_rn(a.z, a.w);
    __half2 h2 = __floats2half2_rn(b.x, b.y);
    __half2 h3 = __floats2half2_rn(b.z, b.w);
    float2 f0 = __half22float2(h0);
    float2 f1 = __half22float2(h1);
    float2 f2 = __half22float2(h2);
    float2 f3 = __half22float2(h3);
    __half2 l0 = __floats2half2_rn(a.x - f0.x, a.y - f0.y);
    __half2 l1 = __floats2half2_rn(a.z - f1.x, a.w - f1.y);
    __half2 l2 = __floats2half2_rn(b.x - f2.x, b.y - f2.y);
    __half2 l3 = __floats2half2_rn(b.z - f3.x, b.w - f3.y);
    hi.x = *(uint32_t*)&h0; hi.y = *(uint32_t*)&h1;
    hi.z = *(uint32_t*)&h2; hi.w = *(uint32_t*)&h3;
    lo.x = *(uint32_t*)&l0; lo.y = *(uint32_t*)&l1;
    lo.z = *(uint32_t*)&l2; lo.w = *(uint32_t*)&l3;
}

// ============================================================
// Warp-specialized split-fp16 NT-GEMM, XOR-swizzled smem (conflict-free).
// Tiles: 128 rows x 64B (32 halves); chunk c at (c ^ ((r>>1)&3)).
// 384 threads: warps 0-7 consumers, 8-11 producers. 3-stage ring.
// ============================================================
#define TILEB 8192                   // 128 * 64B
#define STGB  (4*TILEB)              // A_hi, A_lo, B_hi, B_lo
#define NSTG  3
#define GEMM_SMEM (NSTG*STGB)        // 98304

template<bool BIAS>
__global__ __launch_bounds__(384, 1)
void gemm_ws(const float* __restrict__ A, long Ab, int lda,
             const float* __restrict__ B, long Bb, int ldb,
             float* __restrict__ C, long Cb, long Cs, int ldc,
             const float* __restrict__ bias, int Kd, int ksp)
{
    extern __shared__ __align__(16) char smc[];

    const int tid  = threadIdx.x;
    const int lane = tid & 31;
    const int wid  = tid >> 5;

    const int zb = blockIdx.z / ksp;
    const int zs = blockIdx.z % ksp;
    A += (size_t)zb * Ab + (size_t)zs * Kd;
    B += (size_t)zb * Bb + (size_t)zs * Kd;
    C += (size_t)zb * Cb + (size_t)zs * Cs;
    const int m0 = blockIdx.y * 128;
    const int n0 = blockIdx.x * 128;
    const int iters = Kd / 32;

    if (wid >= 8) {
        // ================= producers (4 warps) =================
        const int ptid = tid - 256;
        const float* Aip = A + (size_t)m0 * lda;
        const float* Bip = B + (size_t)n0 * ldb;

        for (int it = 0; it < iters; it++) {
            const int s = it % NSTG;
            if (it >= NSTG) BAR_SYNC(4 + s);          // EMPTY(s)
            const int k0 = it * 32;
            char* stg = smc + s * STGB;
            #pragma unroll
            for (int p = 0; p < 4; p++) {
                int idx = ptid + p * 128;             // 0..511
                int r = idx >> 2, c = idx & 3;
                int sw = (c ^ ((r >> 1) & 3)) * 16;
                {
                    const float* src = Aip + (size_t)r * lda + k0 + c * 8;
                    float4 v0 = *(const float4*)src;
                    float4 v1 = *(const float4*)(src + 4);
                    uint4 hi, lo;
                    cvt_split16(v0, v1, hi, lo);
                    *(uint4*)(stg + r * 64 + sw) = hi;
                    *(uint4*)(stg + TILEB + r * 64 + sw) = lo;
                }
                {
                    const float* src = Bip + (size_t)r * ldb + k0 + c * 8;
                    float4 v0 = *(const float4*)src;
                    float4 v1 = *(const float4*)(src + 4);
                    uint4 hi, lo;
                    cvt_split16(v0, v1, hi, lo);
                    *(uint4*)(stg + 2*TILEB + r * 64 + sw) = hi;
                    *(uint4*)(stg + 3*TILEB + r * 64 + sw) = lo;
                }
            }
            BAR_ARRIVE(1 + s);                        // FULL(s)
        }
    } else {
        // ================= consumers (8 warps) =================
        const int wm = wid >> 2;
        const int wn = wid & 3;
        const int g  = lane >> 2;
        const int tig = lane & 3;
        const uint32_t sbase = smem_u32(smc);

        float acc[4][4][4];
        #pragma unroll
        for (int i = 0; i < 4; i++)
            #pragma unroll
            for (int j = 0; j < 4; j++)
                #pragma unroll
                for (int v = 0; v < 4; v++) acc[i][j][v] = 0.f;

        for (int it = 0; it < iters; it++) {
            const int s = it % NSTG;
            BAR_SYNC(1 + s);                          // FULL(s)
            const uint32_t stg = sbase + s * STGB;

            #pragma unroll
            for (int ks = 0; ks < 2; ks++) {
                uint32_t ah[4][4], al[4][4], bh[4][2], bl[4][2];
                const int cA = ks * 2 + (lane >> 4);
                #pragma unroll
                for (int mi = 0; mi < 4; mi++) {
                    int r = wm * 64 + mi * 16 + (lane & 15);
                    uint32_t off = (uint32_t)(r * 64 + ((cA ^ ((r >> 1) & 3)) << 4));
                    ldsm4(ah[mi], stg + off);
                    ldsm4(al[mi], stg + TILEB + off);
                }
                const int cB = ks * 2 + ((lane >> 3) & 1);
                #pragma unroll
                for (int ni = 0; ni < 4; ni++) {
                    int r = wn * 32 + ni * 8 + (lane & 7);
                    uint32_t off = (uint32_t)(r * 64 + ((cB ^ ((r >> 1) & 3)) << 4));
                    ldsm2(bh[ni], stg + 2*TILEB + off);
                    ldsm2(bl[ni], stg + 3*TILEB + off);
                }
                #pragma unroll
                for (int mi = 0; mi < 4; mi++)
                    #pragma unroll
                    for (int ni = 0; ni < 4; ni++) {
                        mma16816(acc[mi][ni], ah[mi], bh[ni]);
                        mma16816(acc[mi][ni], ah[mi], bl[ni]);
                        mma16816(acc[mi][ni], al[mi], bh[ni]);
                    }
            }
            BAR_ARRIVE(4 + s);                        // EMPTY(s)
        }

        // ---- epilogue ----
        #pragma unroll
        for (int mi = 0; mi < 4; mi++) {
            const int r0 = m0 + wm * 64 + mi * 16 + g;
            #pragma unroll
            for (int ni = 0; ni < 4; ni++) {
                const int col = n0 + wn * 32 + ni * 8 + tig * 2;
                float2 v0, v1;
                v0.x = acc[mi][ni][0]; v0.y = acc[mi][ni][1];
                v1.x = acc[mi][ni][2]; v1.y = acc[mi][ni][3];
                if (BIAS) {
                    float2 bv = *(const float2*)(bias + col);
                    v0.x += bv.x; v0.y += bv.y;
                    v1.x += bv.x; v1.y += bv.y;
                }
                *(float2*)(C + (size_t)r0 * ldc + col) = v0;
                *(float2*)(C + (size_t)(r0 + 8) * ldc + col) = v1;
            }
        }
    }
}

// ============================================================
// proj transpose: [L,K] -> [K,L]
// ============================================================
__global__ __launch_bounds__(256)
void transpose_proj(const float* __restrict__ pk, const float* __restrict__ pv,
                    float* __restrict__ okt, float* __restrict__ ovt)
{
    __shared__ float t[32][33];
    const float* src = blockIdx.z ? pv : pk;
    float* dst       = blockIdx.z ? ovt : okt;
    int k0 = blockIdx.x * 32, l0 = blockIdx.y * 32;
    int tx = threadIdx.x, ty = threadIdx.y;
    #pragma unroll
    for (int i = 0; i < 32; i += 8)
        t[ty + i][tx] = src[(size_t)(l0 + ty + i) * KK + k0 + tx];
    __syncthreads();
    #pragma unroll
    for (int i = 0; i < 32; i += 8)
        dst[(size_t)(k0 + ty + i) * LL + l0 + tx] = t[tx][ty + i];
}

// ============================================================
// add split-K partials
// ============================================================
__global__ __launch_bounds__(256)
void add2(const float* __restrict__ a, const float* __restrict__ b,
          float* __restrict__ o, int n4)
{
    int i = blockIdx.x * blockDim.x + threadIdx.x;
    if (i >= n4) return;
    float4 x = *(const float4*)(a + i * 4);
    float4 y = *(const float4*)(b + i * 4);
    x.x += y.x; x.y += y.y; x.z += y.z; x.w += y.w;
    *(float4*)(o + i * 4) = x;
}

// ============================================================
// MMA attention, XOR-swizzled smem (128B rows, c ^ (r&7)).
// CTA = (b, h, 128 q-rows); 8 warps x 16-row tiles.
// ============================================================
#define AQH 0
#define AQL 16384
#define AKH 32768
#define AKL 65536
#define AVH 98304
#define AVL 131072
#define ATTN_SMEM 163840

__global__ __launch_bounds__(256, 1)
void attn_mma()
{
    extern __shared__ __align__(16) char smc[];
    const uint32_t base = smem_u32(smc);

    const int b  = blockIdx.z;
    const int h  = blockIdx.y;
    const int l0 = blockIdx.x * 128;
    const int tid  = threadIdx.x;
    const int lane = tid & 31;
    const int wy   = tid >> 5;
    const int g    = lane >> 2;
    const int tig  = lane & 3;

    // ---- fill Q (plain-reshape gather) ----
    #pragma unroll
    for (int it = 0; it < 4; it++) {
        int idx = tid + it * 256;                  // 0..1023
        int r = idx >> 3, c = idx & 7;
        int l = l0 + r;
        const float* src = g_q + ((size_t)(b * LL) + h * 128 + (l >> 4)) * DD
                               + (l & 15) * DH + c * 8;
        float4 v0 = *(const float4*)src;
        float4 v1 = *(const float4*)(src + 4);
        uint4 hi, lo;
        cvt_split16(v0, v1, hi, lo);
        int sw = r * 128 + ((c ^ (r & 7)) << 4);
        *(uint4*)(smc + AQH + sw) = hi;
        *(uint4*)(smc + AQL + sw) = lo;
    }
    // ---- fill K ----
    #pragma unroll
    for (int it = 0; it < 8; it++) {
        int idx = tid + it * 256;                  // 0..2047
        int r = idx >> 3, c = idx & 7;
        const float* src = &g_keys[((size_t)b * KK + r) * DD + h * DH + c * 8];
        float4 v0 = *(const float4*)src;
        float4 v1 = *(const float4*)(src + 4);
        uint4 hi, lo;
        cvt_split16(v0, v1, hi, lo);
        int sw = r * 128 + ((c ^ (r & 7)) << 4);
        *(uint4*)(smc + AKH + sw) = hi;
        *(uint4*)(smc + AKL + sw) = lo;
    }
    // ---- fill V ----
    #pragma unroll
    for (int it = 0; it < 8; it++) {
        int idx = tid + it * 256;
        int r = idx >> 3, c = idx & 7;
        const float* src = &g_vals[((size_t)b * KK + r) * DD + h * DH + c * 8];
        float4 v0 = *(const float4*)src;
        float4 v1 = *(const float4*)(src + 4);
        uint4 hi, lo;
        cvt_split16(v0, v1, hi, lo);
        int sw = r * 128 + ((c ^ (r & 7)) << 4);
        *(uint4*)(smc + AVH + sw) = hi;
        *(uint4*)(smc + AVL + sw) = lo;
    }
    __syncthreads();

    const int m0w = wy * 16;

    // ---- Q A-fragments (4 k-steps of 16, hi+lo) ----
    uint32_t qa_h[4][4], qa_l[4][4];
    {
        int r = m0w + (lane & 15);
        #pragma unroll
        for (int kt = 0; kt < 4; kt++) {
            int c = kt * 2 + (lane >> 4);
            uint32_t off = (uint32_t)(r * 128 + ((c ^ (r & 7)) << 4));
            ldsm4(qa_h[kt], base + AQH + off);
            ldsm4(qa_l[kt], base + AQL + off);
        }
    }

    // ---- S = Q K^T ----
    float acc[32][4];
    #pragma unroll
    for (int nt = 0; nt < 32; nt++)
        #pragma unroll
        for (int v = 0; v < 4; v++) acc[nt][v] = 0.f;

    #pragma unroll
    for (int nt = 0; nt < 32; nt++) {
        int r = nt * 8 + (lane & 7);
        int c0 = (lane >> 3);                       // 0..3
        uint32_t off1 = (uint32_t)(r * 128 + ((c0 ^ (r & 7)) << 4));
        uint32_t off2 = (uint32_t)(r * 128 + (((c0 + 4) ^ (r & 7)) << 4));
        uint32_t kh[8], kl[8];
        ldsm4(kh,     base + AKH + off1);
        ldsm4(kh + 4, base + AKH + off2);
        ldsm4(kl,     base + AKL + off1);
        ldsm4(kl + 4, base + AKL + off2);
        #pragma unroll
        for (int kt = 0; kt < 4; kt++) {
            mma16816(acc[nt], qa_h[kt], kh + kt * 2);
            mma16816(acc[nt], qa_h[kt], kl + kt * 2);
            mma16816(acc[nt], qa_l[kt], kh + kt * 2);
        }
    }

    // ---- softmax (rows g and g+8) ----
    const float SC = 0.125f;
    float mx0 = -1e30f, mx1 = -1e30f;
    #pragma unroll
    for (int nt = 0; nt < 32; nt++) {
        mx0 = fmaxf(mx0, fmaxf(acc[nt][0], acc[nt][1]));
        mx1 = fmaxf(mx1, fmaxf(acc[nt][2], acc[nt][3]));
    }
    #pragma unroll
    for (int o = 1; o <= 2; o <<= 1) {
        mx0 = fmaxf(mx0, __shfl_xor_sync(0xffffffffu, mx0, o));
        mx1 = fmaxf(mx1, __shfl_xor_sync(0xffffffffu, mx1, o));
    }
    const float b0 = mx0 * SC, b1 = mx1 * SC;
    float s0 = 0.f, s1 = 0.f;
    #pragma unroll
    for (int nt = 0; nt < 32; nt++) {
        acc[nt][0] = __expf(acc[nt][0] * SC - b0);
        acc[nt][1] = __expf(acc[nt][1] * SC - b0);
        acc[nt][2] = __expf(acc[nt][2] * SC - b1);
        acc[nt][3] = __expf(acc[nt][3] * SC - b1);
        s0 += acc[nt][0] + acc[nt][1];
        s1 += acc[nt][2] + acc[nt][3];
    }
    #pragma unroll
    for (int o = 1; o <= 2; o <<= 1) {
        s0 += __shfl_xor_sync(0xffffffffu, s0, o);
        s1 += __shfl_xor_sync(0xffffffffu, s1, o);
    }
    const float inv0 = 1.f / s0, inv1 = 1.f / s1;

    // ---- O = P V ----
    float oac[8][4];
    #pragma unroll
    for (int nj = 0; nj < 8; nj++)
        #pragma unroll
        for (int v = 0; v < 4; v++) oac[nj][v] = 0.f;

    #pragma unroll
    for (int kt = 0; kt < 16; kt++) {
        uint32_t ph[4], pl[4];
        #pragma unroll
        for (int half_ = 0; half_ < 2; half_++) {
            const float* c = acc[2 * kt + half_];
            __half2 h0 = __floats2half2_rn(c[0], c[1]);
            __half2 h1 = __floats2half2_rn(c[2], c[3]);
            float2 f0 = __half22float2(h0);
            float2 f1 = __half22float2(h1);
            __half2 e0 = __floats2half2_rn(c[0] - f0.x, c[1] - f0.y);
            __half2 e1 = __floats2half2_rn(c[2] - f1.x, c[3] - f1.y);
            ph[half_ * 2 + 0] = *(uint32_t*)&h0;
            ph[half_ * 2 + 1] = *(uint32_t*)&h1;
            pl[half_ * 2 + 0] = *(uint32_t*)&e0;
            pl[half_ * 2 + 1] = *(uint32_t*)&e1;
        }
        int rv = kt * 16 + (lane & 15);
        #pragma unroll
        for (int nj = 0; nj < 8; nj++) {
            uint32_t off = (uint32_t)(rv * 128 + ((nj ^ (rv & 7)) << 4));
            uint32_t vh[2], vl[2];
            ldsm2t(vh, base + AVH + off);
            ldsm2t(vl, base + AVL + off);
            mma16816(oac[nj], ph, vh);
            mma16816(oac[nj], ph, vl);
            mma16816(oac[nj], pl, vh);
        }
    }

    // ---- epilogue ----
    {
        const int r0 = l0 + m0w + g;
        const size_t orow = ((size_t)(b * LL) + r0) * DD + h * DH;
        #pragma unroll
        for (int nj = 0; nj < 8; nj++) {
            float2 v0, v1;
            v0.x = oac[nj][0] * inv0; v0.y = oac[nj][1] * inv0;
            v1.x = oac[nj][2] * inv1; v1.y = oac[nj][3] * inv1;
            *(float2*)&g_ctx[orow + nj * 8 + tig * 2] = v0;
            *(float2*)&g_ctx[orow + (size_t)8 * DD + nj * 8 + tig * 2] = v1;
        }
    }
}

// ============================================================
extern "C" void kernel_launch(void* const* d_in, const int* in_sizes, int n_in,
                              void* d_out, int out_size)
{
    const float* x      = (const float*)d_in[0];
    const float* Wq     = (const float*)d_in[1];
    const float* Wk     = (const float*)d_in[2];
    const float* Wv     = (const float*)d_in[3];
    const float* proj_k = (const float*)d_in[4];
    const float* proj_v = (const float*)d_in[5];
    const float* Wo     = (const float*)d_in[6];
    const float* bo     = (const float*)d_in[7];
    float* out = (float*)d_out;

    float *q, *xkt, *xvt, *projkt, *projvt, *keys2, *vals2, *keys, *vals, *ctx;
    cudaGetSymbolAddress((void**)&q,      g_q);
    cudaGetSymbolAddress((void**)&xkt,    g_xkt);
    cudaGetSymbolAddress((void**)&xvt,    g_xvt);
    cudaGetSymbolAddress((void**)&projkt, g_projkt);
    cudaGetSymbolAddress((void**)&projvt, g_projvt);
    cudaGetSymbolAddress((void**)&keys2,  g_keys2);
    cudaGetSymbolAddress((void**)&vals2,  g_vals2);
    cudaGetSymbolAddress((void**)&keys,   g_keys);
    cudaGetSymbolAddress((void**)&vals,   g_vals);
    cudaGetSymbolAddress((void**)&ctx,    g_ctx);

    cudaFuncSetAttribute(gemm_ws<false>, cudaFuncAttributeMaxDynamicSharedMemorySize, GEMM_SMEM);
    cudaFuncSetAttribute(gemm_ws<true>,  cudaFuncAttributeMaxDynamicSharedMemorySize, GEMM_SMEM);
    cudaFuncSetAttribute(attn_mma, cudaFuncAttributeMaxDynamicSharedMemorySize, ATTN_SMEM);

    // proj_k / proj_v -> transposed [K,L]
    transpose_proj<<<dim3(KK/32, LL/32, 2), dim3(32, 8)>>>(proj_k, proj_v, projkt, projvt);

    // q = x @ Wq^T
    gemm_ws<false><<<dim3(DD/128, MROWS/128, 1), 384, GEMM_SMEM>>>(
        x, 0, DD, Wq, 0, DD, q, 0, 0, DD, nullptr, DD, 1);

    // xkt[b] = Wk x_b^T : [D, L]
    gemm_ws<false><<<dim3(LL/128, DD/128, BB), 384, GEMM_SMEM>>>(
        Wk, 0, DD, x, (long)LL*DD, DD, xkt, (long)DD*LL, 0, LL, nullptr, DD, 1);

    // xvt[b]
    gemm_ws<false><<<dim3(LL/128, DD/128, BB), 384, GEMM_SMEM>>>(
        Wv, 0, DD, x, (long)LL*DD, DD, xvt, (long)DD*LL, 0, LL, nullptr, DD, 1);

    // keys partials [zs][b][K,D] = projkt x xkt^T  (split-K over L)
    gemm_ws<false><<<dim3(DD/128, KK/128, BB*2), 384, GEMM_SMEM>>>(
        projkt, 0, LL, xkt, (long)DD*LL, LL,
        keys2, (long)KK*DD, (long)BB*KK*DD, DD, nullptr, LL/2, 2);

    // vals partials [zs][b][K,D]
    gemm_ws<false><<<dim3(DD/128, KK/128, BB*2), 384, GEMM_SMEM>>>(
        projvt, 0, LL, xvt, (long)DD*LL, LL,
        vals2, (long)KK*DD, (long)BB*KK*DD, DD, nullptr, LL/2, 2);

    add2<<<(BB*KK*DD/4 + 255)/256, 256>>>(keys2, keys2 + (size_t)BB*KK*DD, keys, BB*KK*DD/4);
    add2<<<(BB*KK*DD/4 + 255)/256, 256>>>(vals2, vals2 + (size_t)BB*KK*DD, vals, BB*KK*DD/4);

    // MMA attention
    attn_mma<<<dim3(LL/128, HH, BB), 256, ATTN_SMEM>>>();

    // out = ctx @ Wo^T + bo
    gemm_ws<true><<<dim3(DD/128, MROWS/128, 1), 384, GEMM_SMEM>>>(
        ctx, 0, DD, Wo, 0, DD, out, 0, 0, DD, bo, DD, 1);
}

// round 9
// speedup vs baseline: 1.7378x; 1.1715x over previous
#include <cuda_runtime.h>
#include <cuda_fp16.h>
#include <cstdint>
#include <math.h>

#define BB 4
#define LL 2048
#define DD 1024
#define HH 16
#define KK 256
#define DH 64
#define MROWS (BB*LL)   // 8192

// ---- scratch (device globals; no runtime allocation allowed) ----
__device__ float g_q[BB*LL*DD];        // x @ Wq^T            [B,L,D]
__device__ float g_xkt[BB*DD*LL];      // (x @ Wk^T)^T        [B,D,L]
__device__ float g_xvt[BB*DD*LL];      // (x @ Wv^T)^T        [B,D,L]
__device__ float g_projkt[KK*LL];      // proj_k^T            [K,L]
__device__ float g_projvt[KK*LL];      // proj_v^T            [K,L]
__device__ float g_keys2[2*BB*KK*DD];  // split-K partials
__device__ float g_vals2[2*BB*KK*DD];
__device__ float g_keys[BB*KK*DD];     // keys [B,K,D]
__device__ float g_vals[BB*KK*DD];     // vals [B,K,D]
__device__ float g_ctx[BB*LL*DD];      // attention out       [B,L,D]

// ============================================================
// helpers
// ============================================================
__device__ __forceinline__ uint32_t smem_u32(const void* p) {
    uint32_t a;
    asm("{ .reg .u64 t; cvta.to.shared.u64 t, %1; cvt.u32.u64 %0, t; }"
        : "=r"(a) : "l"(p));
    return a;
}
__device__ __forceinline__ void ldsm4(uint32_t* r, uint32_t addr) {
    asm volatile("ldmatrix.sync.aligned.m8n8.x4.shared.b16 {%0,%1,%2,%3}, [%4];"
        : "=r"(r[0]), "=r"(r[1]), "=r"(r[2]), "=r"(r[3]) : "r"(addr));
}
__device__ __forceinline__ void ldsm2(uint32_t* r, uint32_t addr) {
    asm volatile("ldmatrix.sync.aligned.m8n8.x2.shared.b16 {%0,%1}, [%2];"
        : "=r"(r[0]), "=r"(r[1]) : "r"(addr));
}
__device__ __forceinline__ void ldsm2t(uint32_t* r, uint32_t addr) {
    asm volatile("ldmatrix.sync.aligned.m8n8.x2.trans.shared.b16 {%0,%1}, [%2];"
        : "=r"(r[0]), "=r"(r[1]) : "r"(addr));
}
__device__ __forceinline__ void mma16816(float* c, const uint32_t* a, const uint32_t* b) {
    asm volatile(
        "mma.sync.aligned.m16n8k16.row.col.f32.f16.f16.f32 "
        "{%0,%1,%2,%3}, {%4,%5,%6,%7}, {%8,%9}, {%0,%1,%2,%3};"
        : "+f"(c[0]), "+f"(c[1]), "+f"(c[2]), "+f"(c[3])
        : "r"(a[0]), "r"(a[1]), "r"(a[2]), "r"(a[3]), "r"(b[0]), "r"(b[1]));
}
#define BAR_SYNC(id)   asm volatile("bar.sync %0, 384;"   :: "r"(id) : "memory")
#define BAR_ARRIVE(id) asm volatile("bar.arrive %0, 384;" :: "r"(id) : "memory")

// split 8 f32 -> 16B hi chunk + 16B lo chunk
__device__ __forceinline__ void cvt_split16(float4 a, float4 b, uint4& hi, uint4& lo) {
    __half2 h0 = __floats2half2_rn(a.x, a.y);
    __half2 h1 = __floats2half2_rn(a.z, a.w);
    __half2 h2 = __floats2half2_rn(b.x, b.y);
    __half2 h3 = __floats2half2_rn(b.z, b.w);
    float2 f0 = __half22float2(h0);
    float2 f1 = __half22float2(h1);
    float2 f2 = __half22float2(h2);
    float2 f3 = __half22float2(h3);
    __half2 l0 = __floats2half2_rn(a.x - f0.x, a.y - f0.y);
    __half2 l1 = __floats2half2_rn(a.z - f1.x, a.w - f1.y);
    __half2 l2 = __floats2half2_rn(b.x - f2.x, b.y - f2.y);
    __half2 l3 = __floats2half2_rn(b.z - f3.x, b.w - f3.y);
    hi.x = *(uint32_t*)&h0; hi.y = *(uint32_t*)&h1;
    hi.z = *(uint32_t*)&h2; hi.w = *(uint32_t*)&h3;
    lo.x = *(uint32_t*)&l0; lo.y = *(uint32_t*)&l1;
    lo.z = *(uint32_t*)&l2; lo.w = *(uint32_t*)&l3;
}
// round 8 f32 -> 16B fp16 chunk (hi only)
__device__ __forceinline__ void cvt_hi16(float4 a, float4 b, uint4& hi) {
    __half2 h0 = __floats2half2_rn(a.x, a.y);
    __half2 h1 = __floats2half2_rn(a.z, a.w);
    __half2 h2 = __floats2half2_rn(b.x, b.y);
    __half2 h3 = __floats2half2_rn(b.z, b.w);
    hi.x = *(uint32_t*)&h0; hi.y = *(uint32_t*)&h1;
    hi.z = *(uint32_t*)&h2; hi.w = *(uint32_t*)&h3;
}

// ============================================================
// Warp-specialized 2-MMA split GEMM:  C = Ah*Bh + Ah*Bl
// (A rounded to fp16; B hi/lo split; dropped Al*Bh term ~1.5e-4 rel).
// XOR-swizzled smem tiles: 128 rows x 64B, chunk c at (c ^ ((r>>1)&3)).
// 384 threads: warps 0-7 consumers, 8-11 producers. 3-stage ring.
// Consumer loads ALL fragments for the stage up-front (reg double-buffer).
// ============================================================
#define TILEB 8192                   // 128 * 64B
#define STGB  (3*TILEB)              // A_hi, B_hi, B_lo
#define NSTG  3
#define GEMM_SMEM (NSTG*STGB)        // 73728

template<bool BIAS>
__global__ __launch_bounds__(384, 1)
void gemm_ws(const float* __restrict__ A, long Ab, int lda,
             const float* __restrict__ B, long Bb, int ldb,
             float* __restrict__ C, long Cb, long Cs, int ldc,
             const float* __restrict__ bias, int Kd, int ksp)
{
    extern __shared__ __align__(16) char smc[];

    const int tid  = threadIdx.x;
    const int lane = tid & 31;
    const int wid  = tid >> 5;

    const int zb = blockIdx.z / ksp;
    const int zs = blockIdx.z % ksp;
    A += (size_t)zb * Ab + (size_t)zs * Kd;
    B += (size_t)zb * Bb + (size_t)zs * Kd;
    C += (size_t)zb * Cb + (size_t)zs * Cs;
    const int m0 = blockIdx.y * 128;
    const int n0 = blockIdx.x * 128;
    const int iters = Kd / 32;

    if (wid >= 8) {
        // ================= producers (4 warps) =================
        const int ptid = tid - 256;
        const float* Aip = A + (size_t)m0 * lda;
        const float* Bip = B + (size_t)n0 * ldb;

        for (int it = 0; it < iters; it++) {
            const int s = it % NSTG;
            if (it >= NSTG) BAR_SYNC(4 + s);          // EMPTY(s)
            const int k0 = it * 32;
            char* stg = smc + s * STGB;
            #pragma unroll
            for (int p = 0; p < 4; p++) {
                int idx = ptid + p * 128;             // 0..511
                int r = idx >> 2, c = idx & 3;
                int sw = (c ^ ((r >> 1) & 3)) * 16;
                {
                    const float* src = Aip + (size_t)r * lda + k0 + c * 8;
                    float4 v0 = *(const float4*)src;
                    float4 v1 = *(const float4*)(src + 4);
                    uint4 hi;
                    cvt_hi16(v0, v1, hi);
                    *(uint4*)(stg + r * 64 + sw) = hi;
                }
                {
                    const float* src = Bip + (size_t)r * ldb + k0 + c * 8;
                    float4 v0 = *(const float4*)src;
                    float4 v1 = *(const float4*)(src + 4);
                    uint4 hi, lo;
                    cvt_split16(v0, v1, hi, lo);
                    *(uint4*)(stg + TILEB + r * 64 + sw) = hi;
                    *(uint4*)(stg + 2*TILEB + r * 64 + sw) = lo;
                }
            }
            BAR_ARRIVE(1 + s);                        // FULL(s)
        }
    } else {
        // ================= consumers (8 warps) =================
        const int wm = wid >> 2;
        const int wn = wid & 3;
        const int g  = lane >> 2;
        const int tig = lane & 3;
        const uint32_t sbase = smem_u32(smc);

        float acc[4][4][4];
        #pragma unroll
        for (int i = 0; i < 4; i++)
            #pragma unroll
            for (int j = 0; j < 4; j++)
                #pragma unroll
                for (int v = 0; v < 4; v++) acc[i][j][v] = 0.f;

        for (int it = 0; it < iters; it++) {
            const int s = it % NSTG;
            BAR_SYNC(1 + s);                          // FULL(s)
            const uint32_t stg = sbase + s * STGB;

            // ---- load ALL fragments for this stage (both ks) up-front ----
            uint32_t ah[2][4][4], bh[2][4][2], bl[2][4][2];
            #pragma unroll
            for (int ks = 0; ks < 2; ks++) {
                const int cA = ks * 2 + (lane >> 4);
                #pragma unroll
                for (int mi = 0; mi < 4; mi++) {
                    int r = wm * 64 + mi * 16 + (lane & 15);
                    uint32_t off = (uint32_t)(r * 64 + ((cA ^ ((r >> 1) & 3)) << 4));
                    ldsm4(ah[ks][mi], stg + off);
                }
                const int cB = ks * 2 + ((lane >> 3) & 1);
                #pragma unroll
                for (int ni = 0; ni < 4; ni++) {
                    int r = wn * 32 + ni * 8 + (lane & 7);
                    uint32_t off = (uint32_t)(r * 64 + ((cB ^ ((r >> 1) & 3)) << 4));
                    ldsm2(bh[ks][ni], stg + TILEB + off);
                    ldsm2(bl[ks][ni], stg + 2*TILEB + off);
                }
            }
            // ---- MMAs: 2 per (mi,ni,ks) ----
            #pragma unroll
            for (int ks = 0; ks < 2; ks++)
                #pragma unroll
                for (int mi = 0; mi < 4; mi++)
                    #pragma unroll
                    for (int ni = 0; ni < 4; ni++) {
                        mma16816(acc[mi][ni], ah[ks][mi], bh[ks][ni]);
                        mma16816(acc[mi][ni], ah[ks][mi], bl[ks][ni]);
                    }
            BAR_ARRIVE(4 + s);                        // EMPTY(s)
        }

        // ---- epilogue ----
        #pragma unroll
        for (int mi = 0; mi < 4; mi++) {
            const int r0 = m0 + wm * 64 + mi * 16 + g;
            #pragma unroll
            for (int ni = 0; ni < 4; ni++) {
                const int col = n0 + wn * 32 + ni * 8 + tig * 2;
                float2 v0, v1;
                v0.x = acc[mi][ni][0]; v0.y = acc[mi][ni][1];
                v1.x = acc[mi][ni][2]; v1.y = acc[mi][ni][3];
                if (BIAS) {
                    float2 bv = *(const float2*)(bias + col);
                    v0.x += bv.x; v0.y += bv.y;
                    v1.x += bv.x; v1.y += bv.y;
                }
                *(float2*)(C + (size_t)r0 * ldc + col) = v0;
                *(float2*)(C + (size_t)(r0 + 8) * ldc + col) = v1;
            }
        }
    }
}

// ============================================================
// proj transpose: [L,K] -> [K,L]
// ============================================================
__global__ __launch_bounds__(256)
void transpose_proj(const float* __restrict__ pk, const float* __restrict__ pv,
                    float* __restrict__ okt, float* __restrict__ ovt)
{
    __shared__ float t[32][33];
    const float* src = blockIdx.z ? pv : pk;
    float* dst       = blockIdx.z ? ovt : okt;
    int k0 = blockIdx.x * 32, l0 = blockIdx.y * 32;
    int tx = threadIdx.x, ty = threadIdx.y;
    #pragma unroll
    for (int i = 0; i < 32; i += 8)
        t[ty + i][tx] = src[(size_t)(l0 + ty + i) * KK + k0 + tx];
    __syncthreads();
    #pragma unroll
    for (int i = 0; i < 32; i += 8)
        dst[(size_t)(k0 + ty + i) * LL + l0 + tx] = t[tx][ty + i];
}

// ============================================================
// add split-K partials
// ============================================================
__global__ __launch_bounds__(256)
void add2(const float* __restrict__ a, const float* __restrict__ b,
          float* __restrict__ o, int n4)
{
    int i = blockIdx.x * blockDim.x + threadIdx.x;
    if (i >= n4) return;
    float4 x = *(const float4*)(a + i * 4);
    float4 y = *(const float4*)(b + i * 4);
    x.x += y.x; x.y += y.y; x.z += y.z; x.w += y.w;
    *(float4*)(o + i * 4) = x;
}

// ============================================================
// MMA attention (R8-verified, keeps full 3-MMA split), XOR-swizzled smem.
// ============================================================
#define AQH 0
#define AQL 16384
#define AKH 32768
#define AKL 65536
#define AVH 98304
#define AVL 131072
#define ATTN_SMEM 163840

__global__ __launch_bounds__(256, 1)
void attn_mma()
{
    extern __shared__ __align__(16) char smc[];
    const uint32_t base = smem_u32(smc);

    const int b  = blockIdx.z;
    const int h  = blockIdx.y;
    const int l0 = blockIdx.x * 128;
    const int tid  = threadIdx.x;
    const int lane = tid & 31;
    const int wy   = tid >> 5;
    const int g    = lane >> 2;
    const int tig  = lane & 3;

    #pragma unroll
    for (int it = 0; it < 4; it++) {
        int idx = tid + it * 256;
        int r = idx >> 3, c = idx & 7;
        int l = l0 + r;
        const float* src = g_q + ((size_t)(b * LL) + h * 128 + (l >> 4)) * DD
                               + (l & 15) * DH + c * 8;
        float4 v0 = *(const float4*)src;
        float4 v1 = *(const float4*)(src + 4);
        uint4 hi, lo;
        cvt_split16(v0, v1, hi, lo);
        int sw = r * 128 + ((c ^ (r & 7)) << 4);
        *(uint4*)(smc + AQH + sw) = hi;
        *(uint4*)(smc + AQL + sw) = lo;
    }
    #pragma unroll
    for (int it = 0; it < 8; it++) {
        int idx = tid + it * 256;
        int r = idx >> 3, c = idx & 7;
        const float* src = &g_keys[((size_t)b * KK + r) * DD + h * DH + c * 8];
        float4 v0 = *(const float4*)src;
        float4 v1 = *(const float4*)(src + 4);
        uint4 hi, lo;
        cvt_split16(v0, v1, hi, lo);
        int sw = r * 128 + ((c ^ (r & 7)) << 4);
        *(uint4*)(smc + AKH + sw) = hi;
        *(uint4*)(smc + AKL + sw) = lo;
    }
    #pragma unroll
    for (int it = 0; it < 8; it++) {
        int idx = tid + it * 256;
        int r = idx >> 3, c = idx & 7;
        const float* src = &g_vals[((size_t)b * KK + r) * DD + h * DH + c * 8];
        float4 v0 = *(const float4*)src;
        float4 v1 = *(const float4*)(src + 4);
        uint4 hi, lo;
        cvt_split16(v0, v1, hi, lo);
        int sw = r * 128 + ((c ^ (r & 7)) << 4);
        *(uint4*)(smc + AVH + sw) = hi;
        *(uint4*)(smc + AVL + sw) = lo;
    }
    __syncthreads();

    const int m0w = wy * 16;

    uint32_t qa_h[4][4], qa_l[4][4];
    {
        int r = m0w + (lane & 15);
        #pragma unroll
        for (int kt = 0; kt < 4; kt++) {
            int c = kt * 2 + (lane >> 4);
            uint32_t off = (uint32_t)(r * 128 + ((c ^ (r & 7)) << 4));
            ldsm4(qa_h[kt], base + AQH + off);
            ldsm4(qa_l[kt], base + AQL + off);
        }
    }

    float acc[32][4];
    #pragma unroll
    for (int nt = 0; nt < 32; nt++)
        #pragma unroll
        for (int v = 0; v < 4; v++) acc[nt][v] = 0.f;

    #pragma unroll
    for (int nt = 0; nt < 32; nt++) {
        int r = nt * 8 + (lane & 7);
        int c0 = (lane >> 3);
        uint32_t off1 = (uint32_t)(r * 128 + ((c0 ^ (r & 7)) << 4));
        uint32_t off2 = (uint32_t)(r * 128 + (((c0 + 4) ^ (r & 7)) << 4));
        uint32_t kh[8], kl[8];
        ldsm4(kh,     base + AKH + off1);
        ldsm4(kh + 4, base + AKH + off2);
        ldsm4(kl,     base + AKL + off1);
        ldsm4(kl + 4, base + AKL + off2);
        #pragma unroll
        for (int kt = 0; kt < 4; kt++) {
            mma16816(acc[nt], qa_h[kt], kh + kt * 2);
            mma16816(acc[nt], qa_h[kt], kl + kt * 2);
            mma16816(acc[nt], qa_l[kt], kh + kt * 2);
        }
    }

    const float SC = 0.125f;
    float mx0 = -1e30f, mx1 = -1e30f;
    #pragma unroll
    for (int nt = 0; nt < 32; nt++) {
        mx0 = fmaxf(mx0, fmaxf(acc[nt][0], acc[nt][1]));
        mx1 = fmaxf(mx1, fmaxf(acc[nt][2], acc[nt][3]));
    }
    #pragma unroll
    for (int o = 1; o <= 2; o <<= 1) {
        mx0 = fmaxf(mx0, __shfl_xor_sync(0xffffffffu, mx0, o));
        mx1 = fmaxf(mx1, __shfl_xor_sync(0xffffffffu, mx1, o));
    }
    const float b0 = mx0 * SC, b1 = mx1 * SC;
    float s0 = 0.f, s1 = 0.f;
    #pragma unroll
    for (int nt = 0; nt < 32; nt++) {
        acc[nt][0] = __expf(acc[nt][0] * SC - b0);
        acc[nt][1] = __expf(acc[nt][1] * SC - b0);
        acc[nt][2] = __expf(acc[nt][2] * SC - b1);
        acc[nt][3] = __expf(acc[nt][3] * SC - b1);
        s0 += acc[nt][0] + acc[nt][1];
        s1 += acc[nt][2] + acc[nt][3];
    }
    #pragma unroll
    for (int o = 1; o <= 2; o <<= 1) {
        s0 += __shfl_xor_sync(0xffffffffu, s0, o);
        s1 += __shfl_xor_sync(0xffffffffu, s1, o);
    }
    const float inv0 = 1.f / s0, inv1 = 1.f / s1;

    float oac[8][4];
    #pragma unroll
    for (int nj = 0; nj < 8; nj++)
        #pragma unroll
        for (int v = 0; v < 4; v++) oac[nj][v] = 0.f;

    #pragma unroll
    for (int kt = 0; kt < 16; kt++) {
        uint32_t ph[4], pl[4];
        #pragma unroll
        for (int half_ = 0; half_ < 2; half_++) {
            const float* c = acc[2 * kt + half_];
            __half2 h0 = __floats2half2_rn(c[0], c[1]);
            __half2 h1 = __floats2half2_rn(c[2], c[3]);
            float2 f0 = __half22float2(h0);
            float2 f1 = __half22float2(h1);
            __half2 e0 = __floats2half2_rn(c[0] - f0.x, c[1] - f0.y);
            __half2 e1 = __floats2half2_rn(c[2] - f1.x, c[3] - f1.y);
            ph[half_ * 2 + 0] = *(uint32_t*)&h0;
            ph[half_ * 2 + 1] = *(uint32_t*)&h1;
            pl[half_ * 2 + 0] = *(uint32_t*)&e0;
            pl[half_ * 2 + 1] = *(uint32_t*)&e1;
        }
        int rv = kt * 16 + (lane & 15);
        #pragma unroll
        for (int nj = 0; nj < 8; nj++) {
            uint32_t off = (uint32_t)(rv * 128 + ((nj ^ (rv & 7)) << 4));
            uint32_t vh[2], vl[2];
            ldsm2t(vh, base + AVH + off);
            ldsm2t(vl, base + AVL + off);
            mma16816(oac[nj], ph, vh);
            mma16816(oac[nj], ph, vl);
            mma16816(oac[nj], pl, vh);
        }
    }

    {
        const int r0 = l0 + m0w + g;
        const size_t orow = ((size_t)(b * LL) + r0) * DD + h * DH;
        #pragma unroll
        for (int nj = 0; nj < 8; nj++) {
            float2 v0, v1;
            v0.x = oac[nj][0] * inv0; v0.y = oac[nj][1] * inv0;
            v1.x = oac[nj][2] * inv1; v1.y = oac[nj][3] * inv1;
            *(float2*)&g_ctx[orow + nj * 8 + tig * 2] = v0;
            *(float2*)&g_ctx[orow + (size_t)8 * DD + nj * 8 + tig * 2] = v1;
        }
    }
}

// ============================================================
extern "C" void kernel_launch(void* const* d_in, const int* in_sizes, int n_in,
                              void* d_out, int out_size)
{
    const float* x      = (const float*)d_in[0];
    const float* Wq     = (const float*)d_in[1];
    const float* Wk     = (const float*)d_in[2];
    const float* Wv     = (const float*)d_in[3];
    const float* proj_k = (const float*)d_in[4];
    const float* proj_v = (const float*)d_in[5];
    const float* Wo     = (const float*)d_in[6];
    const float* bo     = (const float*)d_in[7];
    float* out = (float*)d_out;

    float *q, *xkt, *xvt, *projkt, *projvt, *keys2, *vals2, *keys, *vals, *ctx;
    cudaGetSymbolAddress((void**)&q,      g_q);
    cudaGetSymbolAddress((void**)&xkt,    g_xkt);
    cudaGetSymbolAddress((void**)&xvt,    g_xvt);
    cudaGetSymbolAddress((void**)&projkt, g_projkt);
    cudaGetSymbolAddress((void**)&projvt, g_projvt);
    cudaGetSymbolAddress((void**)&keys2,  g_keys2);
    cudaGetSymbolAddress((void**)&vals2,  g_vals2);
    cudaGetSymbolAddress((void**)&keys,   g_keys);
    cudaGetSymbolAddress((void**)&vals,   g_vals);
    cudaGetSymbolAddress((void**)&ctx,    g_ctx);

    cudaFuncSetAttribute(gemm_ws<false>, cudaFuncAttributeMaxDynamicSharedMemorySize, GEMM_SMEM);
    cudaFuncSetAttribute(gemm_ws<true>,  cudaFuncAttributeMaxDynamicSharedMemorySize, GEMM_SMEM);
    cudaFuncSetAttribute(attn_mma, cudaFuncAttributeMaxDynamicSharedMemorySize, ATTN_SMEM);

    // proj_k / proj_v -> transposed [K,L]
    transpose_proj<<<dim3(KK/32, LL/32, 2), dim3(32, 8)>>>(proj_k, proj_v, projkt, projvt);

    // q = x @ Wq^T
    gemm_ws<false><<<dim3(DD/128, MROWS/128, 1), 384, GEMM_SMEM>>>(
        x, 0, DD, Wq, 0, DD, q, 0, 0, DD, nullptr, DD, 1);

    // xkt[b] = Wk x_b^T : [D, L]
    gemm_ws<false><<<dim3(LL/128, DD/128, BB), 384, GEMM_SMEM>>>(
        Wk, 0, DD, x, (long)LL*DD, DD, xkt, (long)DD*LL, 0, LL, nullptr, DD, 1);

    // xvt[b]
    gemm_ws<false><<<dim3(LL/128, DD/128, BB), 384, GEMM_SMEM>>>(
        Wv, 0, DD, x, (long)LL*DD, DD, xvt, (long)DD*LL, 0, LL, nullptr, DD, 1);

    // keys partials [zs][b][K,D] = projkt x xkt^T  (split-K over L)
    gemm_ws<false><<<dim3(DD/128, KK/128, BB*2), 384, GEMM_SMEM>>>(
        projkt, 0, LL, xkt, (long)DD*LL, LL,
        keys2, (long)KK*DD, (long)BB*KK*DD, DD, nullptr, LL/2, 2);

    // vals partials [zs][b][K,D]
    gemm_ws<false><<<dim3(DD/128, KK/128, BB*2), 384, GEMM_SMEM>>>(
        projvt, 0, LL, xvt, (long)DD*LL, LL,
        vals2, (long)KK*DD, (long)BB*KK*DD, DD, nullptr, LL/2, 2);

    add2<<<(BB*KK*DD/4 + 255)/256, 256>>>(keys2, keys2 + (size_t)BB*KK*DD, keys, BB*KK*DD/4);
    add2<<<(BB*KK*DD/4 + 255)/256, 256>>>(vals2, vals2 + (size_t)BB*KK*DD, vals, BB*KK*DD/4);

    // MMA attention
    attn_mma<<<dim3(LL/128, HH, BB), 256, ATTN_SMEM>>>();

    // out = ctx @ Wo^T + bo
    gemm_ws<true><<<dim3(DD/128, MROWS/128, 1), 384, GEMM_SMEM>>>(
        ctx, 0, DD, Wo, 0, DD, out, 0, 0, DD, bo, DD, 1);
}